// round 13
// baseline (speedup 1.0000x reference)
#include <cuda_runtime.h>
#include <math.h>

#define B_ 8
#define C_ 384
#define H_ 14
#define W_ 14
#define N_ 196
#define HEADS_ 12
#define RH_ 7
#define RW_ 7
#define S_ 49
#define ST_ 58
#define M_ (B_*N_)     // 1568

#define CDIV(a,b) (((a)+(b)-1)/(b))

// ---------------- scratch (device globals; no allocation allowed) ----------
__device__ float g_xh[M_*C_];
__device__ float g_q [M_*C_];
__device__ float g_t1[M_*C_];
__device__ float g_t2[B_*S_*C_];
__device__ float g_offp[B_*S_*2*N_];
__device__ float g_K [M_*C_];                       // xh @ Wk^T (no bias)
__device__ float g_Vh[(size_t)B_*HEADS_*N_*32];     // xh @ Wv^T, head-blocked [b,h,t,d]
__device__ float g_P [(size_t)B_*HEADS_*N_*N_];     // q.K0 per (b,h): [n,n']
__device__ float g_A [(size_t)B_*HEADS_*N_*N_];     // attn scattered: [b,h,n,t]
__device__ float g_ov[M_*C_];
__device__ float g_y [M_*C_];

__constant__ float c_offy[9] = {0.f,-1.f,-1.f,-1.f,0.f,1.f,1.f,1.f,0.f};
__constant__ float c_offx[9] = {-1.f,-1.f,0.f,1.f,1.f,1.f,0.f,-1.f,0.f};

__device__ __forceinline__ float gelu_f(float v){
    return 0.5f*v*(1.0f+erff(v*0.70710678118654752f));
}

// ---------------- fused q/K0/Vh GEMM over shared A = xh --------------------
__global__ __launch_bounds__(256) void qkv_kernel(
    const float* __restrict__ Wq, const float* __restrict__ bq,
    const float* __restrict__ Wk, const float* __restrict__ Wv)
{
    __shared__ float As[16][68];
    __shared__ float Bs[16][68];
    const int which = blockIdx.z;
    const float* __restrict__ Bm = (which==0) ? Wq : (which==1) ? Wk : Wv;

    const int m0 = blockIdx.y*64, n0 = blockIdx.x*64;
    const int tid = threadIdx.x;
    const int tx = tid & 15, ty = tid >> 4;

    float acc[4][4];
    #pragma unroll
    for (int i=0;i<4;i++)
        #pragma unroll
        for (int j=0;j<4;j++) acc[i][j]=0.f;

    float4 pa, pb;
    const float4 z4 = make_float4(0.f,0.f,0.f,0.f);
    const int r = tid>>2, kc = (tid&3)*4;

    auto loadT = [&](int k0){
        int mm = m0 + r;
        pa = (mm<M_) ? *(const float4*)&g_xh[(size_t)mm*384 + k0 + kc] : z4;
        pb = *(const float4*)&Bm[(size_t)(n0+r)*384 + k0 + kc];
    };
    auto storeT = [&](){
        As[kc+0][r]=pa.x; As[kc+1][r]=pa.y; As[kc+2][r]=pa.z; As[kc+3][r]=pa.w;
        Bs[kc+0][r]=pb.x; Bs[kc+1][r]=pb.y; Bs[kc+2][r]=pb.z; Bs[kc+3][r]=pb.w;
    };

    loadT(0); storeT(); __syncthreads();
    for (int k0=16; k0<=384; k0+=16){
        bool more = (k0 < 384);
        if (more) loadT(k0);
        #pragma unroll
        for (int k=0;k<16;k++){
            float4 a = *(const float4*)&As[k][ty*4];
            float4 b = *(const float4*)&Bs[k][tx*4];
            acc[0][0] += a.x*b.x; acc[0][1] += a.x*b.y; acc[0][2] += a.x*b.z; acc[0][3] += a.x*b.w;
            acc[1][0] += a.y*b.x; acc[1][1] += a.y*b.y; acc[1][2] += a.y*b.z; acc[1][3] += a.y*b.w;
            acc[2][0] += a.z*b.x; acc[2][1] += a.z*b.y; acc[2][2] += a.z*b.z; acc[2][3] += a.z*b.w;
            acc[3][0] += a.w*b.x; acc[3][1] += a.w*b.y; acc[3][2] += a.w*b.z; acc[3][3] += a.w*b.w;
        }
        __syncthreads();
        if (more){ storeT(); __syncthreads(); }
    }

    #pragma unroll
    for (int i=0;i<4;i++){
        int mm = m0 + ty*4 + i;
        if (mm>=M_) continue;
        #pragma unroll
        for (int j=0;j<4;j++){
            int nn = n0 + tx*4 + j;
            float v = acc[i][j];
            if (which==0){
                g_q[(size_t)mm*384 + nn] = v + bq[nn];
            } else if (which==1){
                g_K[(size_t)mm*384 + nn] = v;
            } else {
                int bb = mm/196, t = mm - bb*196;
                int hh = nn>>5,  d = nn & 31;
                g_Vh[(((size_t)(bb*12+hh)*196) + t)*32 + d] = v;
            }
        }
    }
}

// ---------------- specialized P kernel v5: float4 fill + 1 tile/thread -----
// grid (4, 96): x = n-quarter (49 rows), y = b*12+h. 384 threads, 325 tiles.
__global__ __launch_bounds__(384) void pk_kernel()
{
    __shared__ float qT[32][52];    // k-major, 49 n (+3 zero pad)
    __shared__ float kT[32][200];   // k-major, 196 t (+4 zero pad)
    const int bh = blockIdx.y;
    const int b  = bh / 12, h = bh - b*12;
    const int n0 = blockIdx.x * 49;
    const int tid = threadIdx.x;
    const float4 z4 = make_float4(0.f,0.f,0.f,0.f);

    for (int i = tid; i < 52*8; i += 384){
        int n = i >> 3, k4 = (i & 7)*4;
        float4 v = (n < 49) ? *(const float4*)&g_q[((size_t)(b*196 + n0 + n))*384 + h*32 + k4] : z4;
        qT[k4+0][n]=v.x; qT[k4+1][n]=v.y; qT[k4+2][n]=v.z; qT[k4+3][n]=v.w;
    }
    for (int i = tid; i < 200*8; i += 384){
        int t = i >> 3, k4 = (i & 7)*4;
        float4 v = (t < 196) ? *(const float4*)&g_K[((size_t)(b*196 + t))*384 + h*32 + k4] : z4;
        kT[k4+0][t]=v.x; kT[k4+1][t]=v.y; kT[k4+2][t]=v.z; kT[k4+3][t]=v.w;
    }
    __syncthreads();

    if (tid < 325){
        int tn = tid % 13, tt = tid / 13;
        int nn = tn*4, t8 = tt*8;
        float a0[8] = {0,0,0,0,0,0,0,0};
        float a1[8] = {0,0,0,0,0,0,0,0};
        float a2[8] = {0,0,0,0,0,0,0,0};
        float a3[8] = {0,0,0,0,0,0,0,0};
        #pragma unroll 4
        for (int k=0;k<32;k++){
            float4 a  = *(const float4*)&qT[k][nn];
            float4 v0 = *(const float4*)&kT[k][t8];
            float4 v1 = *(const float4*)&kT[k][t8+4];
            a0[0]+=a.x*v0.x; a0[1]+=a.x*v0.y; a0[2]+=a.x*v0.z; a0[3]+=a.x*v0.w;
            a0[4]+=a.x*v1.x; a0[5]+=a.x*v1.y; a0[6]+=a.x*v1.z; a0[7]+=a.x*v1.w;
            a1[0]+=a.y*v0.x; a1[1]+=a.y*v0.y; a1[2]+=a.y*v0.z; a1[3]+=a.y*v0.w;
            a1[4]+=a.y*v1.x; a1[5]+=a.y*v1.y; a1[6]+=a.y*v1.z; a1[7]+=a.y*v1.w;
            a2[0]+=a.z*v0.x; a2[1]+=a.z*v0.y; a2[2]+=a.z*v0.z; a2[3]+=a.z*v0.w;
            a2[4]+=a.z*v1.x; a2[5]+=a.z*v1.y; a2[6]+=a.z*v1.z; a2[7]+=a.z*v1.w;
            a3[0]+=a.w*v0.x; a3[1]+=a.w*v0.y; a3[2]+=a.w*v0.z; a3[3]+=a.w*v0.w;
            a3[4]+=a.w*v1.x; a3[5]+=a.w*v1.y; a3[6]+=a.w*v1.z; a3[7]+=a.w*v1.w;
        }
        bool full = (t8 < 192);
        size_t base = ((size_t)bh*196 + n0 + nn)*196 + t8;
        float* rows[4] = {a0,a1,a2,a3};
        #pragma unroll
        for (int r=0;r<4;r++){
            if (nn+r >= 49) break;
            float* ar = rows[r];
            *(float4*)&g_P[base + (size_t)r*196] =
                make_float4(ar[0],ar[1],ar[2],ar[3]);
            if (full)
                *(float4*)&g_P[base + (size_t)r*196 + 4] =
                    make_float4(ar[4],ar[5],ar[6],ar[7]);
        }
    }
}

// ---------------- AV kernel: ov[b,n,h*32+d] = sum_t A[bh,n,t]*Vh[bh,t,d]+bv
// grid (7, 96): x = 28-row n-block, y = b*12+h. 256 threads = 8n x 32d.
__global__ __launch_bounds__(256) void av_kernel(const float* __restrict__ bv)
{
    __shared__ float VhS[196][33];
    const int bh = blockIdx.y;
    const int b  = bh / 12, h = bh - b*12;
    const int n0 = blockIdx.x * 28;
    const int tid = threadIdx.x;
    const int dn = tid >> 5, d = tid & 31;

    // stage Vh[bh] (196 x 32) via float4
    for (int i = tid; i < 196*8; i += 256){
        int t = i >> 3, d4 = (i & 7)*4;
        float4 v = *(const float4*)&g_Vh[(((size_t)bh*196) + t)*32 + d4];
        VhS[t][d4+0]=v.x; VhS[t][d4+1]=v.y; VhS[t][d4+2]=v.z; VhS[t][d4+3]=v.w;
    }
    __syncthreads();

    float bvv = bv[h*32 + d];
    for (int nn = dn; nn < 28; nn += 8){
        int n = n0 + nn;
        const float* Ar = g_A + (((size_t)bh*196) + n)*196;
        float acc = bvv;
        #pragma unroll 4
        for (int t=0; t<196; t++)
            acc += Ar[t]*VhS[t][d];
        g_ov[((size_t)(b*196 + n))*384 + h*32 + d] = acc;
    }
}

// ---------------- templated batched tiled GEMM (general) -------------------
template<int BM, int BN>
__global__ __launch_bounds__((BM/4)*(BN/4)) void gemm_t(
    const float* __restrict__ A, const float* __restrict__ Bm,
    const float* __restrict__ bias, float* __restrict__ C,
    int M, int N, int K, int lda, int ldb, int ldc,
    long long aB, long long bB, long long cB, long long biasB,
    long long aH, long long bH, long long cH, long long biasH,
    int transB, int ep, float scale)
{
    constexpr int T  = (BM/4)*(BN/4);
    constexpr int NA = (BM*4)/T;
    constexpr int NB = (BN*4)/T;
    __shared__ float As[16][BM+4];
    __shared__ float Bs[16][BN+4];

    const int zb = blockIdx.z / 12, zh = blockIdx.z % 12;
    A  += zb*aB + zh*aH;
    Bm += zb*bB + zh*bH;
    C  += zb*cB + zh*cH;
    if (bias) bias += zb*biasB + zh*biasH;

    const int m0 = blockIdx.y*BM, n0 = blockIdx.x*BN;
    const int tid = threadIdx.x;
    const int tx = tid % (BN/4), ty = tid / (BN/4);

    float acc[4][4];
    #pragma unroll
    for (int i=0;i<4;i++)
        #pragma unroll
        for (int j=0;j<4;j++) acc[i][j]=0.f;

    float4 pa[NA], pb[NB];
    const float4 z4 = make_float4(0.f,0.f,0.f,0.f);

    auto loadT = [&](int k0){
        #pragma unroll
        for (int u=0;u<NA;u++){
            int f = tid + u*T;
            int r = f>>2, kc = (f&3)*4;
            int mm = m0 + r;
            pa[u] = (mm<M && k0+kc<K) ? *(const float4*)&A[(long long)mm*lda + k0 + kc] : z4;
        }
        if (transB){
            #pragma unroll
            for (int u=0;u<NB;u++){
                int f = tid + u*T;
                int r = f>>2, kc = (f&3)*4;
                int nn = n0 + r;
                pb[u] = (nn<N && k0+kc<K) ? *(const float4*)&Bm[(long long)nn*ldb + k0 + kc] : z4;
            }
        } else {
            #pragma unroll
            for (int u=0;u<NB;u++){
                int f = tid + u*T;
                int kk = f/(BN/4), nc = (f%(BN/4))*4;
                int nn = n0 + nc;
                pb[u] = (k0+kk<K && nn<N) ? *(const float4*)&Bm[(long long)(k0+kk)*ldb + nn] : z4;
            }
        }
    };
    auto storeT = [&](){
        #pragma unroll
        for (int u=0;u<NA;u++){
            int f = tid + u*T;
            int r = f>>2, kc = (f&3)*4;
            As[kc+0][r]=pa[u].x; As[kc+1][r]=pa[u].y;
            As[kc+2][r]=pa[u].z; As[kc+3][r]=pa[u].w;
        }
        if (transB){
            #pragma unroll
            for (int u=0;u<NB;u++){
                int f = tid + u*T;
                int r = f>>2, kc = (f&3)*4;
                Bs[kc+0][r]=pb[u].x; Bs[kc+1][r]=pb[u].y;
                Bs[kc+2][r]=pb[u].z; Bs[kc+3][r]=pb[u].w;
            }
        } else {
            #pragma unroll
            for (int u=0;u<NB;u++){
                int f = tid + u*T;
                int kk = f/(BN/4), nc = (f%(BN/4))*4;
                *(float4*)&Bs[kk][nc] = pb[u];
            }
        }
    };

    const int KT = CDIV(K,16)*16;
    loadT(0); storeT(); __syncthreads();
    for (int k0=16; k0<=KT; k0+=16){
        bool more = (k0 < KT);
        if (more) loadT(k0);
        #pragma unroll
        for (int k=0;k<16;k++){
            float4 a = *(const float4*)&As[k][ty*4];
            float4 b = *(const float4*)&Bs[k][tx*4];
            acc[0][0] += a.x*b.x; acc[0][1] += a.x*b.y; acc[0][2] += a.x*b.z; acc[0][3] += a.x*b.w;
            acc[1][0] += a.y*b.x; acc[1][1] += a.y*b.y; acc[1][2] += a.y*b.z; acc[1][3] += a.y*b.w;
            acc[2][0] += a.z*b.x; acc[2][1] += a.z*b.y; acc[2][2] += a.z*b.z; acc[2][3] += a.z*b.w;
            acc[3][0] += a.w*b.x; acc[3][1] += a.w*b.y; acc[3][2] += a.w*b.z; acc[3][3] += a.w*b.w;
        }
        __syncthreads();
        if (more){ storeT(); __syncthreads(); }
    }

    #pragma unroll
    for (int i=0;i<4;i++){
        int mm = m0 + ty*4 + i;
        if (mm>=M) continue;
        #pragma unroll
        for (int j=0;j<4;j++){
            int nn = n0 + tx*4 + j;
            if (nn>=N) continue;
            float v = acc[i][j];
            if (bias) v += bias[nn];
            if (ep==1) v = gelu_f(v);
            else if (ep==2) v = tanhf(v)*scale;
            C[(long long)mm*ldc + nn] = v;
        }
    }
}

// ---------------- batched matrix transpose: in [R,Cc] -> out [Cc,R] --------
__global__ __launch_bounds__(256) void transpose_kernel(
    const float* __restrict__ in, float* __restrict__ out, int R, int Cc)
{
    __shared__ float tile[32][33];
    const float* inb = in + (size_t)blockIdx.z * R * Cc;
    float* outb = out + (size_t)blockIdx.z * R * Cc;
    int bx = blockIdx.x*32, by = blockIdx.y*32;
    int tx = threadIdx.x, ty = threadIdx.y;
    #pragma unroll
    for (int i=0;i<32;i+=8){
        int r = by+ty+i, c = bx+tx;
        if (r<R && c<Cc) tile[ty+i][tx] = inb[(size_t)r*Cc + c];
    }
    __syncthreads();
    #pragma unroll
    for (int i=0;i<32;i+=8){
        int c = bx+ty+i, r = by+tx;
        if (c<Cc && r<R) outb[(size_t)c*R + r] = tile[tx][ty+i];
    }
}

// ---------------- depthwise 3x3 s2 conv + LayerNorm + GELU (single pass) ---
__global__ __launch_bounds__(384) void dwln_kernel(
    const float* __restrict__ Wdw, const float* __restrict__ bdw,
    const float* __restrict__ ln_g, const float* __restrict__ ln_b)
{
    __shared__ float red1[13], red2[13];
    int p = blockIdx.x;        // b*49 + s
    int b = p/49, s = p - b*49;
    int oy = s/7, ox = s - oy*7;
    int c = threadIdx.x;       // 0..383
    float acc = bdw[c];
    #pragma unroll
    for (int kh=0;kh<3;kh++){
        int iy = oy*2-1+kh;
        if (iy<0 || iy>=14) continue;
        #pragma unroll
        for (int kw=0;kw<3;kw++){
            int ix = ox*2-1+kw;
            if (ix<0 || ix>=14) continue;
            acc += g_t1[((b*196)+iy*14+ix)*384 + c]*Wdw[c*9+kh*3+kw];
        }
    }
    int lane = c & 31, w = c >> 5;
    float s1 = acc, s2 = acc*acc;
    #pragma unroll
    for (int o=16;o;o>>=1){
        s1 += __shfl_xor_sync(0xffffffffu, s1, o);
        s2 += __shfl_xor_sync(0xffffffffu, s2, o);
    }
    if (lane==0){ red1[w] = s1; red2[w] = s2; }
    __syncthreads();
    if (w==0){
        float u1 = (lane<12)? red1[lane] : 0.f;
        float u2 = (lane<12)? red2[lane] : 0.f;
        #pragma unroll
        for (int o=16;o;o>>=1){
            u1 += __shfl_xor_sync(0xffffffffu, u1, o);
            u2 += __shfl_xor_sync(0xffffffffu, u2, o);
        }
        if (lane==0){ red1[12] = u1; red2[12] = u2; }
    }
    __syncthreads();
    float mu  = red1[12]*(1.0f/384.0f);
    float var = red2[12]*(1.0f/384.0f) - mu*mu;
    float d = acc - mu;
    float tn = d * rsqrtf(var + 1e-5f) * ln_g[c] + ln_b[c];
    g_t2[p*384 + c] = gelu_f(tn);
}

// ---------------- attention v2: co fused + P-gather + softmax + scatter ----
__global__ __launch_bounds__(256) void attn_kernel(
    const float* __restrict__ bk, const float* __restrict__ posembed,
    const float* __restrict__ Wco)
{
    __shared__ float attnS[12*64];
    __shared__ float Aacc [12*196];
    __shared__ float sw   [ST_*4];
    __shared__ float bpy  [ST_], bpx[ST_];
    __shared__ float qbks [12];
    __shared__ float cs   [18];
    __shared__ int   sa   [ST_*4];

    int m = blockIdx.x;
    int b = m / 196, n = m - b*196;
    int ny = n / 14, nx = n - ny*14;
    int tid = threadIdx.x;
    int lane = tid & 31, wid = tid >> 5;

    for (int i = tid; i < 12*196; i += 256) Aacc[i] = 0.f;

    // co[m, o] = tanh(q . Wco[o]) / 14   (warp per output, 18 outputs)
    for (int o = wid; o < 18; o += 8){
        float acc = 0.f;
        #pragma unroll
        for (int k=0;k<12;k++)
            acc += g_q[(size_t)m*384 + lane + 32*k] * Wco[(size_t)o*384 + lane + 32*k];
        #pragma unroll
        for (int of=16;of;of>>=1) acc += __shfl_xor_sync(0xffffffffu, acc, of);
        if (lane==0) cs[o] = tanhf(acc)*(1.0f/14.0f);
    }
    // q . bk per head
    if (tid >= 192 && tid < 204){
        int h = tid - 192;
        float acc = 0.f;
        #pragma unroll 8
        for (int d=0; d<32; d++)
            acc += g_q[m*384 + h*32 + d]*bk[h*32 + d];
        qbks[h] = acc;
    }
    __syncthreads();

    // per-slot sampling setup (needs cs for center slots)
    if (tid < ST_){
        int s = tid;
        float py, px, by, bx;
        if (s < S_){
            int ry = s/7, rx = s - ry*7;
            float offY = g_offp[(b*49+s)*392 + n];
            float offX = g_offp[(b*49+s)*392 + 196 + n];
            float gy = (2.0f*ry)*(2.0f/13.0f) - 1.0f;
            float gx = (2.0f*rx)*(2.0f/13.0f) - 1.0f;
            py = (offY + gy + 1.0f)*6.5f;
            px = (offX + gx + 1.0f)*6.5f;
            by = ((2.0f*ry - (float)ny)*(1.0f/13.0f) - offY + 1.0f)*13.0f;
            bx = ((2.0f*rx - (float)nx)*(1.0f/13.0f) - offX + 1.0f)*13.0f;
        } else {
            int kk = s - S_;
            float coY = cs[kk*2];
            float coX = cs[kk*2 + 1];
            float cpy = fminf(fmaxf((float)ny + c_offy[kk], 0.f), 14.f);
            float cpx = fminf(fmaxf((float)nx + c_offx[kk], 0.f), 14.f);
            float cgy = cpy*(2.0f/13.0f) - 1.0f;
            float cgx = cpx*(2.0f/13.0f) - 1.0f;
            py = (coY + cgy + 1.0f)*6.5f;
            px = (coX + cgx + 1.0f)*6.5f;
            by = (coY - (float)ny + 1.0f)*13.0f;
            bx = (coX - (float)nx + 1.0f)*13.0f;
        }
        bpy[s] = by; bpx[s] = bx;
        float y0f = floorf(py), x0f = floorf(px);
        float wy1 = py - y0f, wx1 = px - x0f;
        int y0 = (int)y0f, x0 = (int)x0f;
        float wts[4] = {(1.f-wy1)*(1.f-wx1), (1.f-wy1)*wx1, wy1*(1.f-wx1), wy1*wx1};
        const int dys[4] = {0,0,1,1};
        const int dxs[4] = {0,1,0,1};
        #pragma unroll
        for (int i=0;i<4;i++){
            int yy = y0+dys[i], xx = x0+dxs[i];
            bool valid = (yy>=0 && yy<=13 && xx>=0 && xx<=13);
            int yc = min(max(yy,0),13), xc = min(max(xx,0),13);
            sw[s*4+i] = valid ? wts[i] : 0.f;
            sa[s*4+i] = yc*14 + xc;
        }
    }
    __syncthreads();

    // logits = rel-pos bias (bilinear) + sum_i w_i * P[b,h,n,t_i] + q.bk
    for (int p2 = tid; p2 < 12*ST_; p2 += 256){
        int h = p2 / ST_, s = p2 - h*ST_;
        float py = bpy[s], px = bpx[s];
        float y0f = floorf(py), x0f = floorf(px);
        float wy1 = py - y0f, wx1 = px - x0f;
        int y0 = (int)y0f, x0 = (int)x0f;
        const float* tb = posembed + h*729;
        float acc = qbks[h];
        float wts[4] = {(1.f-wy1)*(1.f-wx1), (1.f-wy1)*wx1, wy1*(1.f-wx1), wy1*wx1};
        const int dys[4]={0,0,1,1}, dxs[4]={0,1,0,1};
        #pragma unroll
        for (int i=0;i<4;i++){
            int yy=y0+dys[i], xx=x0+dxs[i];
            if (yy>=0 && yy<=26 && xx>=0 && xx<=26)
                acc += tb[yy*27+xx]*wts[i];
        }
        const float* Pn = g_P + (((size_t)(b*12+h)*196 + n)*196);
        acc += sw[s*4+0]*Pn[sa[s*4+0]] + sw[s*4+1]*Pn[sa[s*4+1]]
             + sw[s*4+2]*Pn[sa[s*4+2]] + sw[s*4+3]*Pn[sa[s*4+3]];
        attnS[h*64+s] = acc;
    }
    __syncthreads();

    for (int h = wid; h < 12; h += 8){
        float v0 = attnS[h*64 + lane];
        float v1 = (lane < ST_-32) ? attnS[h*64 + 32 + lane] : -1e30f;
        float mx = fmaxf(v0, v1);
        #pragma unroll
        for (int o=16;o;o>>=1) mx = fmaxf(mx, __shfl_xor_sync(0xffffffffu, mx, o));
        float e0 = expf(v0 - mx);
        float e1 = (lane < ST_-32) ? expf(v1 - mx) : 0.f;
        float ssum = e0 + e1;
        #pragma unroll
        for (int o=16;o;o>>=1) ssum += __shfl_xor_sync(0xffffffffu, ssum, o);
        float inv = 1.0f/ssum;
        attnS[h*64 + lane] = e0*inv;
        if (lane < ST_-32) attnS[h*64+32+lane] = e1*inv;
    }
    __syncthreads();

    for (int p2 = tid; p2 < 12*ST_; p2 += 256){
        int h = p2 / ST_, s = p2 - h*ST_;
        float a = attnS[h*64+s];
        #pragma unroll
        for (int i=0;i<4;i++)
            atomicAdd(&Aacc[h*196 + sa[s*4+i]], a*sw[s*4+i]);
    }
    __syncthreads();

    for (int i = tid; i < 12*196; i += 256){
        int h = i/196, t = i - h*196;
        g_A[(((size_t)(b*12+h)*196) + n)*196 + t] = Aacc[i];
    }
}

// ---------------------------------------------------------------------------
extern "C" void kernel_launch(void* const* d_in, const int* in_sizes, int n_in,
                              void* d_out, int out_size)
{
    (void)in_sizes; (void)n_in; (void)out_size;
    const float* x   = (const float*)d_in[0];
    const float* Wq  = (const float*)d_in[1];
    const float* bq  = (const float*)d_in[2];
    const float* Wk  = (const float*)d_in[3];
    const float* bk  = (const float*)d_in[4];
    const float* Wv  = (const float*)d_in[5];
    const float* bv  = (const float*)d_in[6];
    const float* Wo1 = (const float*)d_in[7];
    const float* bo1 = (const float*)d_in[8];
    const float* Wdw = (const float*)d_in[9];
    const float* bdw = (const float*)d_in[10];
    const float* ln_g= (const float*)d_in[11];
    const float* ln_b= (const float*)d_in[12];
    const float* Wo2 = (const float*)d_in[13];
    const float* Wco = (const float*)d_in[14];
    const float* pe  = (const float*)d_in[15];
    const float* Wp  = (const float*)d_in[16];
    const float* bp  = (const float*)d_in[17];
    float* out = (float*)d_out;

    float *xh,*q,*t1,*t2,*offp,*Vh,*A,*ov,*y;
    cudaGetSymbolAddress((void**)&xh,  g_xh);
    cudaGetSymbolAddress((void**)&q,   g_q);
    cudaGetSymbolAddress((void**)&t1,  g_t1);
    cudaGetSymbolAddress((void**)&t2,  g_t2);
    cudaGetSymbolAddress((void**)&offp,g_offp);
    cudaGetSymbolAddress((void**)&Vh,  g_Vh);
    cudaGetSymbolAddress((void**)&A,   g_A);
    cudaGetSymbolAddress((void**)&ov,  g_ov);
    cudaGetSymbolAddress((void**)&y,   g_y);

    dim3 tb(32,8);

    // 1) x (B,C,H,W) -> xh (B,N,C)
    transpose_kernel<<<dim3(CDIV(196,32), CDIV(384,32), B_), tb>>>(x, xh, 384, 196);

    // 2) q, K0, Vh in one fused launch
    qkv_kernel<<<dim3(6,25,3),256>>>(Wq, bq, Wk, Wv);

    // 3) t1 = gelu(q @ Wo1^T + bo1)
    gemm_t<64,64><<<dim3(6,25,1),256>>>(q, Wo1, bo1, t1, M_,384,384, 384,384,384,
                                        0,0,0,0, 0,0,0,0, 1, 1, 0.f);
    // 4) P[b,h,n,t] v5   <-- profiled slot (control, expect ~21us)
    pk_kernel<<<dim3(4,96),384>>>();

    // 5) depthwise conv + LN + gelu -> t2
    dwln_kernel<<<B_*S_, 384>>>(Wdw, bdw, ln_g, ln_b);

    // 6) offp = tanh(t2 @ Wo2^T) * FACTOR/14
    gemm_t<32,32><<<dim3(13,13,1),64>>>(t2, Wo2, nullptr, offp, B_*S_, 392, 384,
                                        384,384,392, 0,0,0,0, 0,0,0,0, 1, 2, 2.0f/14.0f);
    // 7) attention v2 (co fused) -> A
    attn_kernel<<<M_, 256>>>(bk, pe, Wco);

    // 8) ov = A @ Vh + bv  (custom, occupancy-rich)
    av_kernel<<<dim3(7,96),256>>>(bv);

    // 9) y = ov @ Wp^T + bp
    gemm_t<64,64><<<dim3(6,25,1),256>>>(ov, Wp, bp, y, M_,384,384, 384,384,384,
                                        0,0,0,0, 0,0,0,0, 1, 0, 0.f);
    // 10) y (B,N,C) -> out (B,C,H,W)
    transpose_kernel<<<dim3(CDIV(384,32), CDIV(196,32), B_), tb>>>(y, out, 196, 384);
}

// round 14
// speedup vs baseline: 1.1562x; 1.1562x over previous
#include <cuda_runtime.h>
#include <math.h>

#define B_ 8
#define C_ 384
#define H_ 14
#define W_ 14
#define N_ 196
#define HEADS_ 12
#define RH_ 7
#define RW_ 7
#define S_ 49
#define ST_ 58
#define M_ (B_*N_)     // 1568

#define CDIV(a,b) (((a)+(b)-1)/(b))

// ---------------- scratch (device globals; no allocation allowed) ----------
__device__ float g_xh[M_*C_];
__device__ float g_q [M_*C_];
__device__ float g_t1[M_*C_];
__device__ float g_t2[B_*S_*C_];
__device__ float g_offp[B_*S_*2*N_];
__device__ float g_K [M_*C_];                       // xh @ Wk^T (no bias)
__device__ float g_Vh[(size_t)B_*HEADS_*N_*32];     // xh @ Wv^T, head-blocked [b,h,t,d]
__device__ float g_P [(size_t)B_*HEADS_*N_*N_];     // q.K0 per (b,h): [n,n']
__device__ float g_A [(size_t)B_*HEADS_*N_*N_];     // attn scattered: [b,h,n,t]
__device__ float g_ov[M_*C_];
__device__ float g_y [M_*C_];

__constant__ float c_offy[9] = {0.f,-1.f,-1.f,-1.f,0.f,1.f,1.f,1.f,0.f};
__constant__ float c_offx[9] = {-1.f,-1.f,0.f,1.f,1.f,1.f,0.f,-1.f,0.f};

__device__ __forceinline__ float gelu_f(float v){
    return 0.5f*v*(1.0f+erff(v*0.70710678118654752f));
}

// ---------------- fused q/K0/Vh GEMM over shared A = xh --------------------
__global__ __launch_bounds__(256) void qkv_kernel(
    const float* __restrict__ Wq, const float* __restrict__ bq,
    const float* __restrict__ Wk, const float* __restrict__ Wv)
{
    __shared__ float As[16][68];
    __shared__ float Bs[16][68];
    const int which = blockIdx.z;
    const float* __restrict__ Bm = (which==0) ? Wq : (which==1) ? Wk : Wv;

    const int m0 = blockIdx.y*64, n0 = blockIdx.x*64;
    const int tid = threadIdx.x;
    const int tx = tid & 15, ty = tid >> 4;

    float acc[4][4];
    #pragma unroll
    for (int i=0;i<4;i++)
        #pragma unroll
        for (int j=0;j<4;j++) acc[i][j]=0.f;

    float4 pa, pb;
    const float4 z4 = make_float4(0.f,0.f,0.f,0.f);
    const int r = tid>>2, kc = (tid&3)*4;

    auto loadT = [&](int k0){
        int mm = m0 + r;
        pa = (mm<M_) ? *(const float4*)&g_xh[(size_t)mm*384 + k0 + kc] : z4;
        pb = *(const float4*)&Bm[(size_t)(n0+r)*384 + k0 + kc];
    };
    auto storeT = [&](){
        As[kc+0][r]=pa.x; As[kc+1][r]=pa.y; As[kc+2][r]=pa.z; As[kc+3][r]=pa.w;
        Bs[kc+0][r]=pb.x; Bs[kc+1][r]=pb.y; Bs[kc+2][r]=pb.z; Bs[kc+3][r]=pb.w;
    };

    loadT(0); storeT(); __syncthreads();
    for (int k0=16; k0<=384; k0+=16){
        bool more = (k0 < 384);
        if (more) loadT(k0);
        #pragma unroll
        for (int k=0;k<16;k++){
            float4 a = *(const float4*)&As[k][ty*4];
            float4 b = *(const float4*)&Bs[k][tx*4];
            acc[0][0] += a.x*b.x; acc[0][1] += a.x*b.y; acc[0][2] += a.x*b.z; acc[0][3] += a.x*b.w;
            acc[1][0] += a.y*b.x; acc[1][1] += a.y*b.y; acc[1][2] += a.y*b.z; acc[1][3] += a.y*b.w;
            acc[2][0] += a.z*b.x; acc[2][1] += a.z*b.y; acc[2][2] += a.z*b.z; acc[2][3] += a.z*b.w;
            acc[3][0] += a.w*b.x; acc[3][1] += a.w*b.y; acc[3][2] += a.w*b.z; acc[3][3] += a.w*b.w;
        }
        __syncthreads();
        if (more){ storeT(); __syncthreads(); }
    }

    #pragma unroll
    for (int i=0;i<4;i++){
        int mm = m0 + ty*4 + i;
        if (mm>=M_) continue;
        #pragma unroll
        for (int j=0;j<4;j++){
            int nn = n0 + tx*4 + j;
            float v = acc[i][j];
            if (which==0){
                g_q[(size_t)mm*384 + nn] = v + bq[nn];
            } else if (which==1){
                g_K[(size_t)mm*384 + nn] = v;
            } else {
                int bb = mm/196, t = mm - bb*196;
                int hh = nn>>5,  d = nn & 31;
                g_Vh[(((size_t)(bb*12+hh)*196) + t)*32 + d] = v;
            }
        }
    }
}

// ---------------- specialized P kernel v5: float4 fill + 1 tile/thread -----
// grid (4, 96): x = n-quarter (49 rows), y = b*12+h. 384 threads, 325 tiles.
__global__ __launch_bounds__(384) void pk_kernel()
{
    __shared__ float qT[32][52];    // k-major, 49 n (+3 zero pad)
    __shared__ float kT[32][200];   // k-major, 196 t (+4 zero pad)
    const int bh = blockIdx.y;
    const int b  = bh / 12, h = bh - b*12;
    const int n0 = blockIdx.x * 49;
    const int tid = threadIdx.x;
    const float4 z4 = make_float4(0.f,0.f,0.f,0.f);

    for (int i = tid; i < 52*8; i += 384){
        int n = i >> 3, k4 = (i & 7)*4;
        float4 v = (n < 49) ? *(const float4*)&g_q[((size_t)(b*196 + n0 + n))*384 + h*32 + k4] : z4;
        qT[k4+0][n]=v.x; qT[k4+1][n]=v.y; qT[k4+2][n]=v.z; qT[k4+3][n]=v.w;
    }
    for (int i = tid; i < 200*8; i += 384){
        int t = i >> 3, k4 = (i & 7)*4;
        float4 v = (t < 196) ? *(const float4*)&g_K[((size_t)(b*196 + t))*384 + h*32 + k4] : z4;
        kT[k4+0][t]=v.x; kT[k4+1][t]=v.y; kT[k4+2][t]=v.z; kT[k4+3][t]=v.w;
    }
    __syncthreads();

    if (tid < 325){
        int tn = tid % 13, tt = tid / 13;
        int nn = tn*4, t8 = tt*8;
        float a0[8] = {0,0,0,0,0,0,0,0};
        float a1[8] = {0,0,0,0,0,0,0,0};
        float a2[8] = {0,0,0,0,0,0,0,0};
        float a3[8] = {0,0,0,0,0,0,0,0};
        #pragma unroll 4
        for (int k=0;k<32;k++){
            float4 a  = *(const float4*)&qT[k][nn];
            float4 v0 = *(const float4*)&kT[k][t8];
            float4 v1 = *(const float4*)&kT[k][t8+4];
            a0[0]+=a.x*v0.x; a0[1]+=a.x*v0.y; a0[2]+=a.x*v0.z; a0[3]+=a.x*v0.w;
            a0[4]+=a.x*v1.x; a0[5]+=a.x*v1.y; a0[6]+=a.x*v1.z; a0[7]+=a.x*v1.w;
            a1[0]+=a.y*v0.x; a1[1]+=a.y*v0.y; a1[2]+=a.y*v0.z; a1[3]+=a.y*v0.w;
            a1[4]+=a.y*v1.x; a1[5]+=a.y*v1.y; a1[6]+=a.y*v1.z; a1[7]+=a.y*v1.w;
            a2[0]+=a.z*v0.x; a2[1]+=a.z*v0.y; a2[2]+=a.z*v0.z; a2[3]+=a.z*v0.w;
            a2[4]+=a.z*v1.x; a2[5]+=a.z*v1.y; a2[6]+=a.z*v1.z; a2[7]+=a.z*v1.w;
            a3[0]+=a.w*v0.x; a3[1]+=a.w*v0.y; a3[2]+=a.w*v0.z; a3[3]+=a.w*v0.w;
            a3[4]+=a.w*v1.x; a3[5]+=a.w*v1.y; a3[6]+=a.w*v1.z; a3[7]+=a.w*v1.w;
        }
        bool full = (t8 < 192);
        size_t base = ((size_t)bh*196 + n0 + nn)*196 + t8;
        float* rows[4] = {a0,a1,a2,a3};
        #pragma unroll
        for (int r=0;r<4;r++){
            if (nn+r >= 49) break;
            float* ar = rows[r];
            *(float4*)&g_P[base + (size_t)r*196] =
                make_float4(ar[0],ar[1],ar[2],ar[3]);
            if (full)
                *(float4*)&g_P[base + (size_t)r*196 + 4] =
                    make_float4(ar[4],ar[5],ar[6],ar[7]);
        }
    }
}

// ---------------- templated batched tiled GEMM (general) -------------------
template<int BM, int BN>
__global__ __launch_bounds__((BM/4)*(BN/4)) void gemm_t(
    const float* __restrict__ A, const float* __restrict__ Bm,
    const float* __restrict__ bias, float* __restrict__ C,
    int M, int N, int K, int lda, int ldb, int ldc,
    long long aB, long long bB, long long cB, long long biasB,
    long long aH, long long bH, long long cH, long long biasH,
    int transB, int ep, float scale)
{
    constexpr int T  = (BM/4)*(BN/4);
    constexpr int NA = (BM*4)/T;
    constexpr int NB = (BN*4)/T;
    __shared__ float As[16][BM+4];
    __shared__ float Bs[16][BN+4];

    const int zb = blockIdx.z / 12, zh = blockIdx.z % 12;
    A  += zb*aB + zh*aH;
    Bm += zb*bB + zh*bH;
    C  += zb*cB + zh*cH;
    if (bias) bias += zb*biasB + zh*biasH;

    const int m0 = blockIdx.y*BM, n0 = blockIdx.x*BN;
    const int tid = threadIdx.x;
    const int tx = tid % (BN/4), ty = tid / (BN/4);

    float acc[4][4];
    #pragma unroll
    for (int i=0;i<4;i++)
        #pragma unroll
        for (int j=0;j<4;j++) acc[i][j]=0.f;

    float4 pa[NA], pb[NB];
    const float4 z4 = make_float4(0.f,0.f,0.f,0.f);

    auto loadT = [&](int k0){
        #pragma unroll
        for (int u=0;u<NA;u++){
            int f = tid + u*T;
            int r = f>>2, kc = (f&3)*4;
            int mm = m0 + r;
            pa[u] = (mm<M && k0+kc<K) ? *(const float4*)&A[(long long)mm*lda + k0 + kc] : z4;
        }
        if (transB){
            #pragma unroll
            for (int u=0;u<NB;u++){
                int f = tid + u*T;
                int r = f>>2, kc = (f&3)*4;
                int nn = n0 + r;
                pb[u] = (nn<N && k0+kc<K) ? *(const float4*)&Bm[(long long)nn*ldb + k0 + kc] : z4;
            }
        } else {
            #pragma unroll
            for (int u=0;u<NB;u++){
                int f = tid + u*T;
                int kk = f/(BN/4), nc = (f%(BN/4))*4;
                int nn = n0 + nc;
                pb[u] = (k0+kk<K && nn<N) ? *(const float4*)&Bm[(long long)(k0+kk)*ldb + nn] : z4;
            }
        }
    };
    auto storeT = [&](){
        #pragma unroll
        for (int u=0;u<NA;u++){
            int f = tid + u*T;
            int r = f>>2, kc = (f&3)*4;
            As[kc+0][r]=pa[u].x; As[kc+1][r]=pa[u].y;
            As[kc+2][r]=pa[u].z; As[kc+3][r]=pa[u].w;
        }
        if (transB){
            #pragma unroll
            for (int u=0;u<NB;u++){
                int f = tid + u*T;
                int r = f>>2, kc = (f&3)*4;
                Bs[kc+0][r]=pb[u].x; Bs[kc+1][r]=pb[u].y;
                Bs[kc+2][r]=pb[u].z; Bs[kc+3][r]=pb[u].w;
            }
        } else {
            #pragma unroll
            for (int u=0;u<NB;u++){
                int f = tid + u*T;
                int kk = f/(BN/4), nc = (f%(BN/4))*4;
                *(float4*)&Bs[kk][nc] = pb[u];
            }
        }
    };

    const int KT = CDIV(K,16)*16;
    loadT(0); storeT(); __syncthreads();
    for (int k0=16; k0<=KT; k0+=16){
        bool more = (k0 < KT);
        if (more) loadT(k0);
        #pragma unroll
        for (int k=0;k<16;k++){
            float4 a = *(const float4*)&As[k][ty*4];
            float4 b = *(const float4*)&Bs[k][tx*4];
            acc[0][0] += a.x*b.x; acc[0][1] += a.x*b.y; acc[0][2] += a.x*b.z; acc[0][3] += a.x*b.w;
            acc[1][0] += a.y*b.x; acc[1][1] += a.y*b.y; acc[1][2] += a.y*b.z; acc[1][3] += a.y*b.w;
            acc[2][0] += a.z*b.x; acc[2][1] += a.z*b.y; acc[2][2] += a.z*b.z; acc[2][3] += a.z*b.w;
            acc[3][0] += a.w*b.x; acc[3][1] += a.w*b.y; acc[3][2] += a.w*b.z; acc[3][3] += a.w*b.w;
        }
        __syncthreads();
        if (more){ storeT(); __syncthreads(); }
    }

    #pragma unroll
    for (int i=0;i<4;i++){
        int mm = m0 + ty*4 + i;
        if (mm>=M) continue;
        #pragma unroll
        for (int j=0;j<4;j++){
            int nn = n0 + tx*4 + j;
            if (nn>=N) continue;
            float v = acc[i][j];
            if (bias) v += bias[nn];
            if (ep==1) v = gelu_f(v);
            else if (ep==2) v = tanhf(v)*scale;
            C[(long long)mm*ldc + nn] = v;
        }
    }
}

// ---------------- batched matrix transpose: in [R,Cc] -> out [Cc,R] --------
__global__ __launch_bounds__(256) void transpose_kernel(
    const float* __restrict__ in, float* __restrict__ out, int R, int Cc)
{
    __shared__ float tile[32][33];
    const float* inb = in + (size_t)blockIdx.z * R * Cc;
    float* outb = out + (size_t)blockIdx.z * R * Cc;
    int bx = blockIdx.x*32, by = blockIdx.y*32;
    int tx = threadIdx.x, ty = threadIdx.y;
    #pragma unroll
    for (int i=0;i<32;i+=8){
        int r = by+ty+i, c = bx+tx;
        if (r<R && c<Cc) tile[ty+i][tx] = inb[(size_t)r*Cc + c];
    }
    __syncthreads();
    #pragma unroll
    for (int i=0;i<32;i+=8){
        int c = bx+ty+i, r = by+tx;
        if (c<Cc && r<R) outb[(size_t)c*R + r] = tile[tx][ty+i];
    }
}

// ---------------- depthwise 3x3 s2 conv + LayerNorm + GELU (single pass) ---
__global__ __launch_bounds__(384) void dwln_kernel(
    const float* __restrict__ Wdw, const float* __restrict__ bdw,
    const float* __restrict__ ln_g, const float* __restrict__ ln_b)
{
    __shared__ float red1[13], red2[13];
    int p = blockIdx.x;        // b*49 + s
    int b = p/49, s = p - b*49;
    int oy = s/7, ox = s - oy*7;
    int c = threadIdx.x;       // 0..383
    float acc = bdw[c];
    #pragma unroll
    for (int kh=0;kh<3;kh++){
        int iy = oy*2-1+kh;
        if (iy<0 || iy>=14) continue;
        #pragma unroll
        for (int kw=0;kw<3;kw++){
            int ix = ox*2-1+kw;
            if (ix<0 || ix>=14) continue;
            acc += g_t1[((b*196)+iy*14+ix)*384 + c]*Wdw[c*9+kh*3+kw];
        }
    }
    int lane = c & 31, w = c >> 5;
    float s1 = acc, s2 = acc*acc;
    #pragma unroll
    for (int o=16;o;o>>=1){
        s1 += __shfl_xor_sync(0xffffffffu, s1, o);
        s2 += __shfl_xor_sync(0xffffffffu, s2, o);
    }
    if (lane==0){ red1[w] = s1; red2[w] = s2; }
    __syncthreads();
    if (w==0){
        float u1 = (lane<12)? red1[lane] : 0.f;
        float u2 = (lane<12)? red2[lane] : 0.f;
        #pragma unroll
        for (int o=16;o;o>>=1){
            u1 += __shfl_xor_sync(0xffffffffu, u1, o);
            u2 += __shfl_xor_sync(0xffffffffu, u2, o);
        }
        if (lane==0){ red1[12] = u1; red2[12] = u2; }
    }
    __syncthreads();
    float mu  = red1[12]*(1.0f/384.0f);
    float var = red2[12]*(1.0f/384.0f) - mu*mu;
    float d = acc - mu;
    float tn = d * rsqrtf(var + 1e-5f) * ln_g[c] + ln_b[c];
    g_t2[p*384 + c] = gelu_f(tn);
}

// ---------------- attention v3: P staged in smem + co fused ---------------
__global__ __launch_bounds__(256) void attn_kernel(
    const float* __restrict__ bk, const float* __restrict__ posembed,
    const float* __restrict__ Wco)
{
    __shared__ float attnS[12*64];
    __shared__ float Aacc [12*196];
    __shared__ float PnS  [12*196];
    __shared__ float sw   [ST_*4];
    __shared__ float bpy  [ST_], bpx[ST_];
    __shared__ float qbks [12];
    __shared__ float cs   [18];
    __shared__ int   sa   [ST_*4];

    int m = blockIdx.x;
    int b = m / 196, n = m - b*196;
    int ny = n / 14, nx = n - ny*14;
    int tid = threadIdx.x;
    int lane = tid & 31, wid = tid >> 5;

    for (int i = tid; i < 12*196; i += 256) Aacc[i] = 0.f;

    // stage all 12 P rows for token n: coalesced float4 (196 = 49 float4)
    for (int i = tid; i < 12*49; i += 256){
        int h = i / 49, q4 = (i % 49)*4;
        const float* Pn = g_P + (((size_t)(b*12+h)*196 + n)*196);
        float4 v = *(const float4*)&Pn[q4];
        *(float4*)&PnS[h*196 + q4] = v;
    }

    // co[m, o] = tanh(q . Wco[o]) / 14   (warp per output, 18 outputs)
    for (int o = wid; o < 18; o += 8){
        float acc = 0.f;
        #pragma unroll
        for (int k=0;k<12;k++)
            acc += g_q[(size_t)m*384 + lane + 32*k] * Wco[(size_t)o*384 + lane + 32*k];
        #pragma unroll
        for (int of=16;of;of>>=1) acc += __shfl_xor_sync(0xffffffffu, acc, of);
        if (lane==0) cs[o] = tanhf(acc)*(1.0f/14.0f);
    }
    // q . bk per head
    if (tid >= 192 && tid < 204){
        int h = tid - 192;
        float acc = 0.f;
        #pragma unroll 8
        for (int d=0; d<32; d++)
            acc += g_q[m*384 + h*32 + d]*bk[h*32 + d];
        qbks[h] = acc;
    }
    __syncthreads();

    // per-slot sampling setup (needs cs for center slots)
    if (tid < ST_){
        int s = tid;
        float py, px, by, bx;
        if (s < S_){
            int ry = s/7, rx = s - ry*7;
            float offY = g_offp[(b*49+s)*392 + n];
            float offX = g_offp[(b*49+s)*392 + 196 + n];
            float gy = (2.0f*ry)*(2.0f/13.0f) - 1.0f;
            float gx = (2.0f*rx)*(2.0f/13.0f) - 1.0f;
            py = (offY + gy + 1.0f)*6.5f;
            px = (offX + gx + 1.0f)*6.5f;
            by = ((2.0f*ry - (float)ny)*(1.0f/13.0f) - offY + 1.0f)*13.0f;
            bx = ((2.0f*rx - (float)nx)*(1.0f/13.0f) - offX + 1.0f)*13.0f;
        } else {
            int kk = s - S_;
            float coY = cs[kk*2];
            float coX = cs[kk*2 + 1];
            float cpy = fminf(fmaxf((float)ny + c_offy[kk], 0.f), 14.f);
            float cpx = fminf(fmaxf((float)nx + c_offx[kk], 0.f), 14.f);
            float cgy = cpy*(2.0f/13.0f) - 1.0f;
            float cgx = cpx*(2.0f/13.0f) - 1.0f;
            py = (coY + cgy + 1.0f)*6.5f;
            px = (coX + cgx + 1.0f)*6.5f;
            by = (coY - (float)ny + 1.0f)*13.0f;
            bx = (coX - (float)nx + 1.0f)*13.0f;
        }
        bpy[s] = by; bpx[s] = bx;
        float y0f = floorf(py), x0f = floorf(px);
        float wy1 = py - y0f, wx1 = px - x0f;
        int y0 = (int)y0f, x0 = (int)x0f;
        float wts[4] = {(1.f-wy1)*(1.f-wx1), (1.f-wy1)*wx1, wy1*(1.f-wx1), wy1*wx1};
        const int dys[4] = {0,0,1,1};
        const int dxs[4] = {0,1,0,1};
        #pragma unroll
        for (int i=0;i<4;i++){
            int yy = y0+dys[i], xx = x0+dxs[i];
            bool valid = (yy>=0 && yy<=13 && xx>=0 && xx<=13);
            int yc = min(max(yy,0),13), xc = min(max(xx,0),13);
            sw[s*4+i] = valid ? wts[i] : 0.f;
            sa[s*4+i] = yc*14 + xc;
        }
    }
    __syncthreads();

    // logits = rel-pos bias (bilinear) + sum_i w_i * PnS[h][t_i] + q.bk
    for (int p2 = tid; p2 < 12*ST_; p2 += 256){
        int h = p2 / ST_, s = p2 - h*ST_;
        float py = bpy[s], px = bpx[s];
        float y0f = floorf(py), x0f = floorf(px);
        float wy1 = py - y0f, wx1 = px - x0f;
        int y0 = (int)y0f, x0 = (int)x0f;
        const float* tb = posembed + h*729;
        float acc = qbks[h];
        float wts[4] = {(1.f-wy1)*(1.f-wx1), (1.f-wy1)*wx1, wy1*(1.f-wx1), wy1*wx1};
        const int dys[4]={0,0,1,1}, dxs[4]={0,1,0,1};
        #pragma unroll
        for (int i=0;i<4;i++){
            int yy=y0+dys[i], xx=x0+dxs[i];
            if (yy>=0 && yy<=26 && xx>=0 && xx<=26)
                acc += tb[yy*27+xx]*wts[i];
        }
        const float* Pn = PnS + h*196;
        acc += sw[s*4+0]*Pn[sa[s*4+0]] + sw[s*4+1]*Pn[sa[s*4+1]]
             + sw[s*4+2]*Pn[sa[s*4+2]] + sw[s*4+3]*Pn[sa[s*4+3]];
        attnS[h*64+s] = acc;
    }
    __syncthreads();

    for (int h = wid; h < 12; h += 8){
        float v0 = attnS[h*64 + lane];
        float v1 = (lane < ST_-32) ? attnS[h*64 + 32 + lane] : -1e30f;
        float mx = fmaxf(v0, v1);
        #pragma unroll
        for (int o=16;o;o>>=1) mx = fmaxf(mx, __shfl_xor_sync(0xffffffffu, mx, o));
        float e0 = expf(v0 - mx);
        float e1 = (lane < ST_-32) ? expf(v1 - mx) : 0.f;
        float ssum = e0 + e1;
        #pragma unroll
        for (int o=16;o;o>>=1) ssum += __shfl_xor_sync(0xffffffffu, ssum, o);
        float inv = 1.0f/ssum;
        attnS[h*64 + lane] = e0*inv;
        if (lane < ST_-32) attnS[h*64+32+lane] = e1*inv;
    }
    __syncthreads();

    for (int p2 = tid; p2 < 12*ST_; p2 += 256){
        int h = p2 / ST_, s = p2 - h*ST_;
        float a = attnS[h*64+s];
        #pragma unroll
        for (int i=0;i<4;i++)
            atomicAdd(&Aacc[h*196 + sa[s*4+i]], a*sw[s*4+i]);
    }
    __syncthreads();

    for (int i = tid; i < 12*196; i += 256){
        int h = i/196, t = i - h*196;
        g_A[(((size_t)(b*12+h)*196) + n)*196 + t] = Aacc[i];
    }
}

// ---------------------------------------------------------------------------
extern "C" void kernel_launch(void* const* d_in, const int* in_sizes, int n_in,
                              void* d_out, int out_size)
{
    (void)in_sizes; (void)n_in; (void)out_size;
    const float* x   = (const float*)d_in[0];
    const float* Wq  = (const float*)d_in[1];
    const float* bq  = (const float*)d_in[2];
    const float* Wk  = (const float*)d_in[3];
    const float* bk  = (const float*)d_in[4];
    const float* Wv  = (const float*)d_in[5];
    const float* bv  = (const float*)d_in[6];
    const float* Wo1 = (const float*)d_in[7];
    const float* bo1 = (const float*)d_in[8];
    const float* Wdw = (const float*)d_in[9];
    const float* bdw = (const float*)d_in[10];
    const float* ln_g= (const float*)d_in[11];
    const float* ln_b= (const float*)d_in[12];
    const float* Wo2 = (const float*)d_in[13];
    const float* Wco = (const float*)d_in[14];
    const float* pe  = (const float*)d_in[15];
    const float* Wp  = (const float*)d_in[16];
    const float* bp  = (const float*)d_in[17];
    float* out = (float*)d_out;

    float *xh,*q,*t1,*t2,*offp,*Vh,*A,*ov,*y;
    cudaGetSymbolAddress((void**)&xh,  g_xh);
    cudaGetSymbolAddress((void**)&q,   g_q);
    cudaGetSymbolAddress((void**)&t1,  g_t1);
    cudaGetSymbolAddress((void**)&t2,  g_t2);
    cudaGetSymbolAddress((void**)&offp,g_offp);
    cudaGetSymbolAddress((void**)&Vh,  g_Vh);
    cudaGetSymbolAddress((void**)&A,   g_A);
    cudaGetSymbolAddress((void**)&ov,  g_ov);
    cudaGetSymbolAddress((void**)&y,   g_y);

    dim3 tb(32,8);

    // 1) x (B,C,H,W) -> xh (B,N,C)
    transpose_kernel<<<dim3(CDIV(196,32), CDIV(384,32), B_), tb>>>(x, xh, 384, 196);

    // 2) q, K0, Vh in one fused launch
    qkv_kernel<<<dim3(6,25,3),256>>>(Wq, bq, Wk, Wv);

    // 3) t1 = gelu(q @ Wo1^T + bo1)
    gemm_t<64,64><<<dim3(6,25,1),256>>>(q, Wo1, bo1, t1, M_,384,384, 384,384,384,
                                        0,0,0,0, 0,0,0,0, 1, 1, 0.f);
    // 4) P[b,h,n,t] v5   <-- profiled slot (control)
    pk_kernel<<<dim3(4,96),384>>>();

    // 5) depthwise conv + LN + gelu -> t2
    dwln_kernel<<<B_*S_, 384>>>(Wdw, bdw, ln_g, ln_b);

    // 6) offp = tanh(t2 @ Wo2^T) * FACTOR/14
    gemm_t<32,32><<<dim3(13,13,1),64>>>(t2, Wo2, nullptr, offp, B_*S_, 392, 384,
                                        384,384,392, 0,0,0,0, 0,0,0,0, 1, 2, 2.0f/14.0f);
    // 7) attention v3 (P staged in smem) -> A
    attn_kernel<<<M_, 256>>>(bk, pe, Wco);

    // 8) ov[b,n,h*32+d] = sum_t A[b,h,n,t] * Vh[b,h,t,d] + bv
    gemm_t<64,32><<<dim3(1,4,96),128>>>(A, Vh, bv, ov, 196, 32, 196,
                                        196, 32, 384,
                                        12LL*196*196, 12LL*196*32, 196LL*384, 0,
                                        196LL*196, 196LL*32, 32LL, 32LL,
                                        0, 0, 0.f);
    // 9) y = ov @ Wp^T + bp
    gemm_t<64,64><<<dim3(6,25,1),256>>>(ov, Wp, bp, y, M_,384,384, 384,384,384,
                                        0,0,0,0, 0,0,0,0, 1, 0, 0.f);
    // 10) y (B,N,C) -> out (B,C,H,W)
    transpose_kernel<<<dim3(CDIV(384,32), CDIV(196,32), B_), tb>>>(y, out, 196, 384);
}

// round 15
// speedup vs baseline: 1.1945x; 1.0331x over previous
#include <cuda_runtime.h>
#include <math.h>

#define B_ 8
#define C_ 384
#define H_ 14
#define W_ 14
#define N_ 196
#define HEADS_ 12
#define RH_ 7
#define RW_ 7
#define S_ 49
#define ST_ 58
#define M_ (B_*N_)     // 1568

#define CDIV(a,b) (((a)+(b)-1)/(b))

// ---------------- scratch (device globals; no allocation allowed) ----------
__device__ float g_xh[M_*C_];
__device__ float g_q [M_*C_];
__device__ float g_t1[M_*C_];
__device__ float g_t2[B_*S_*C_];
__device__ float g_offp[B_*S_*2*N_];
__device__ float g_K [M_*C_];                       // xh @ Wk^T (no bias)
__device__ float g_Vh[(size_t)B_*HEADS_*N_*32];     // xh @ Wv^T, head-blocked [b,h,t,d]
__device__ float g_P [(size_t)B_*HEADS_*N_*N_];     // q.K0 per (b,h): [n,n']
__device__ float g_A [(size_t)B_*HEADS_*N_*N_];     // attn scattered: [b,h,n,t]
__device__ float g_ov[M_*C_];
__device__ float g_y [M_*C_];

__constant__ float c_offy[9] = {0.f,-1.f,-1.f,-1.f,0.f,1.f,1.f,1.f,0.f};
__constant__ float c_offx[9] = {-1.f,-1.f,0.f,1.f,1.f,1.f,0.f,-1.f,0.f};

__device__ __forceinline__ float gelu_f(float v){
    return 0.5f*v*(1.0f+erff(v*0.70710678118654752f));
}

// ---------------- fused q/K0/Vh GEMM over shared A = xh --------------------
__global__ __launch_bounds__(256) void qkv_kernel(
    const float* __restrict__ Wq, const float* __restrict__ bq,
    const float* __restrict__ Wk, const float* __restrict__ Wv)
{
    __shared__ float As[16][68];
    __shared__ float Bs[16][68];
    const int which = blockIdx.z;
    const float* __restrict__ Bm = (which==0) ? Wq : (which==1) ? Wk : Wv;

    const int m0 = blockIdx.y*64, n0 = blockIdx.x*64;
    const int tid = threadIdx.x;
    const int tx = tid & 15, ty = tid >> 4;

    float acc[4][4];
    #pragma unroll
    for (int i=0;i<4;i++)
        #pragma unroll
        for (int j=0;j<4;j++) acc[i][j]=0.f;

    float4 pa, pb;
    const float4 z4 = make_float4(0.f,0.f,0.f,0.f);
    const int r = tid>>2, kc = (tid&3)*4;

    auto loadT = [&](int k0){
        int mm = m0 + r;
        pa = (mm<M_) ? *(const float4*)&g_xh[(size_t)mm*384 + k0 + kc] : z4;
        pb = *(const float4*)&Bm[(size_t)(n0+r)*384 + k0 + kc];
    };
    auto storeT = [&](){
        As[kc+0][r]=pa.x; As[kc+1][r]=pa.y; As[kc+2][r]=pa.z; As[kc+3][r]=pa.w;
        Bs[kc+0][r]=pb.x; Bs[kc+1][r]=pb.y; Bs[kc+2][r]=pb.z; Bs[kc+3][r]=pb.w;
    };

    loadT(0); storeT(); __syncthreads();
    for (int k0=16; k0<=384; k0+=16){
        bool more = (k0 < 384);
        if (more) loadT(k0);
        #pragma unroll
        for (int k=0;k<16;k++){
            float4 a = *(const float4*)&As[k][ty*4];
            float4 b = *(const float4*)&Bs[k][tx*4];
            acc[0][0] += a.x*b.x; acc[0][1] += a.x*b.y; acc[0][2] += a.x*b.z; acc[0][3] += a.x*b.w;
            acc[1][0] += a.y*b.x; acc[1][1] += a.y*b.y; acc[1][2] += a.y*b.z; acc[1][3] += a.y*b.w;
            acc[2][0] += a.z*b.x; acc[2][1] += a.z*b.y; acc[2][2] += a.z*b.z; acc[2][3] += a.z*b.w;
            acc[3][0] += a.w*b.x; acc[3][1] += a.w*b.y; acc[3][2] += a.w*b.z; acc[3][3] += a.w*b.w;
        }
        __syncthreads();
        if (more){ storeT(); __syncthreads(); }
    }

    #pragma unroll
    for (int i=0;i<4;i++){
        int mm = m0 + ty*4 + i;
        if (mm>=M_) continue;
        #pragma unroll
        for (int j=0;j<4;j++){
            int nn = n0 + tx*4 + j;
            float v = acc[i][j];
            if (which==0){
                g_q[(size_t)mm*384 + nn] = v + bq[nn];
            } else if (which==1){
                g_K[(size_t)mm*384 + nn] = v;
            } else {
                int bb = mm/196, t = mm - bb*196;
                int hh = nn>>5,  d = nn & 31;
                g_Vh[(((size_t)(bb*12+hh)*196) + t)*32 + d] = v;
            }
        }
    }
}

// ---------------- specialized P kernel v5: float4 fill + 1 tile/thread -----
// grid (4, 96): x = n-quarter (49 rows), y = b*12+h. 384 threads, 325 tiles.
__global__ __launch_bounds__(384) void pk_kernel()
{
    __shared__ float qT[32][52];    // k-major, 49 n (+3 zero pad)
    __shared__ float kT[32][200];   // k-major, 196 t (+4 zero pad)
    const int bh = blockIdx.y;
    const int b  = bh / 12, h = bh - b*12;
    const int n0 = blockIdx.x * 49;
    const int tid = threadIdx.x;
    const float4 z4 = make_float4(0.f,0.f,0.f,0.f);

    for (int i = tid; i < 52*8; i += 384){
        int n = i >> 3, k4 = (i & 7)*4;
        float4 v = (n < 49) ? *(const float4*)&g_q[((size_t)(b*196 + n0 + n))*384 + h*32 + k4] : z4;
        qT[k4+0][n]=v.x; qT[k4+1][n]=v.y; qT[k4+2][n]=v.z; qT[k4+3][n]=v.w;
    }
    for (int i = tid; i < 200*8; i += 384){
        int t = i >> 3, k4 = (i & 7)*4;
        float4 v = (t < 196) ? *(const float4*)&g_K[((size_t)(b*196 + t))*384 + h*32 + k4] : z4;
        kT[k4+0][t]=v.x; kT[k4+1][t]=v.y; kT[k4+2][t]=v.z; kT[k4+3][t]=v.w;
    }
    __syncthreads();

    if (tid < 325){
        int tn = tid % 13, tt = tid / 13;
        int nn = tn*4, t8 = tt*8;
        float a0[8] = {0,0,0,0,0,0,0,0};
        float a1[8] = {0,0,0,0,0,0,0,0};
        float a2[8] = {0,0,0,0,0,0,0,0};
        float a3[8] = {0,0,0,0,0,0,0,0};
        #pragma unroll 4
        for (int k=0;k<32;k++){
            float4 a  = *(const float4*)&qT[k][nn];
            float4 v0 = *(const float4*)&kT[k][t8];
            float4 v1 = *(const float4*)&kT[k][t8+4];
            a0[0]+=a.x*v0.x; a0[1]+=a.x*v0.y; a0[2]+=a.x*v0.z; a0[3]+=a.x*v0.w;
            a0[4]+=a.x*v1.x; a0[5]+=a.x*v1.y; a0[6]+=a.x*v1.z; a0[7]+=a.x*v1.w;
            a1[0]+=a.y*v0.x; a1[1]+=a.y*v0.y; a1[2]+=a.y*v0.z; a1[3]+=a.y*v0.w;
            a1[4]+=a.y*v1.x; a1[5]+=a.y*v1.y; a1[6]+=a.y*v1.z; a1[7]+=a.y*v1.w;
            a2[0]+=a.z*v0.x; a2[1]+=a.z*v0.y; a2[2]+=a.z*v0.z; a2[3]+=a.z*v0.w;
            a2[4]+=a.z*v1.x; a2[5]+=a.z*v1.y; a2[6]+=a.z*v1.z; a2[7]+=a.z*v1.w;
            a3[0]+=a.w*v0.x; a3[1]+=a.w*v0.y; a3[2]+=a.w*v0.z; a3[3]+=a.w*v0.w;
            a3[4]+=a.w*v1.x; a3[5]+=a.w*v1.y; a3[6]+=a.w*v1.z; a3[7]+=a.w*v1.w;
        }
        bool full = (t8 < 192);
        size_t base = ((size_t)bh*196 + n0 + nn)*196 + t8;
        float* rows[4] = {a0,a1,a2,a3};
        #pragma unroll
        for (int r=0;r<4;r++){
            if (nn+r >= 49) break;
            float* ar = rows[r];
            *(float4*)&g_P[base + (size_t)r*196] =
                make_float4(ar[0],ar[1],ar[2],ar[3]);
            if (full)
                *(float4*)&g_P[base + (size_t)r*196 + 4] =
                    make_float4(ar[4],ar[5],ar[6],ar[7]);
        }
    }
}

// ---------------- templated batched tiled GEMM (general) -------------------
template<int BM, int BN>
__global__ __launch_bounds__((BM/4)*(BN/4)) void gemm_t(
    const float* __restrict__ A, const float* __restrict__ Bm,
    const float* __restrict__ bias, float* __restrict__ C,
    int M, int N, int K, int lda, int ldb, int ldc,
    long long aB, long long bB, long long cB, long long biasB,
    long long aH, long long bH, long long cH, long long biasH,
    int transB, int ep, float scale)
{
    constexpr int T  = (BM/4)*(BN/4);
    constexpr int NA = (BM*4)/T;
    constexpr int NB = (BN*4)/T;
    __shared__ float As[16][BM+4];
    __shared__ float Bs[16][BN+4];

    const int zb = blockIdx.z / 12, zh = blockIdx.z % 12;
    A  += zb*aB + zh*aH;
    Bm += zb*bB + zh*bH;
    C  += zb*cB + zh*cH;
    if (bias) bias += zb*biasB + zh*biasH;

    const int m0 = blockIdx.y*BM, n0 = blockIdx.x*BN;
    const int tid = threadIdx.x;
    const int tx = tid % (BN/4), ty = tid / (BN/4);

    float acc[4][4];
    #pragma unroll
    for (int i=0;i<4;i++)
        #pragma unroll
        for (int j=0;j<4;j++) acc[i][j]=0.f;

    float4 pa[NA], pb[NB];
    const float4 z4 = make_float4(0.f,0.f,0.f,0.f);

    auto loadT = [&](int k0){
        #pragma unroll
        for (int u=0;u<NA;u++){
            int f = tid + u*T;
            int r = f>>2, kc = (f&3)*4;
            int mm = m0 + r;
            pa[u] = (mm<M && k0+kc<K) ? *(const float4*)&A[(long long)mm*lda + k0 + kc] : z4;
        }
        if (transB){
            #pragma unroll
            for (int u=0;u<NB;u++){
                int f = tid + u*T;
                int r = f>>2, kc = (f&3)*4;
                int nn = n0 + r;
                pb[u] = (nn<N && k0+kc<K) ? *(const float4*)&Bm[(long long)nn*ldb + k0 + kc] : z4;
            }
        } else {
            #pragma unroll
            for (int u=0;u<NB;u++){
                int f = tid + u*T;
                int kk = f/(BN/4), nc = (f%(BN/4))*4;
                int nn = n0 + nc;
                pb[u] = (k0+kk<K && nn<N) ? *(const float4*)&Bm[(long long)(k0+kk)*ldb + nn] : z4;
            }
        }
    };
    auto storeT = [&](){
        #pragma unroll
        for (int u=0;u<NA;u++){
            int f = tid + u*T;
            int r = f>>2, kc = (f&3)*4;
            As[kc+0][r]=pa[u].x; As[kc+1][r]=pa[u].y;
            As[kc+2][r]=pa[u].z; As[kc+3][r]=pa[u].w;
        }
        if (transB){
            #pragma unroll
            for (int u=0;u<NB;u++){
                int f = tid + u*T;
                int r = f>>2, kc = (f&3)*4;
                Bs[kc+0][r]=pb[u].x; Bs[kc+1][r]=pb[u].y;
                Bs[kc+2][r]=pb[u].z; Bs[kc+3][r]=pb[u].w;
            }
        } else {
            #pragma unroll
            for (int u=0;u<NB;u++){
                int f = tid + u*T;
                int kk = f/(BN/4), nc = (f%(BN/4))*4;
                *(float4*)&Bs[kk][nc] = pb[u];
            }
        }
    };

    const int KT = CDIV(K,16)*16;
    loadT(0); storeT(); __syncthreads();
    for (int k0=16; k0<=KT; k0+=16){
        bool more = (k0 < KT);
        if (more) loadT(k0);
        #pragma unroll
        for (int k=0;k<16;k++){
            float4 a = *(const float4*)&As[k][ty*4];
            float4 b = *(const float4*)&Bs[k][tx*4];
            acc[0][0] += a.x*b.x; acc[0][1] += a.x*b.y; acc[0][2] += a.x*b.z; acc[0][3] += a.x*b.w;
            acc[1][0] += a.y*b.x; acc[1][1] += a.y*b.y; acc[1][2] += a.y*b.z; acc[1][3] += a.y*b.w;
            acc[2][0] += a.z*b.x; acc[2][1] += a.z*b.y; acc[2][2] += a.z*b.z; acc[2][3] += a.z*b.w;
            acc[3][0] += a.w*b.x; acc[3][1] += a.w*b.y; acc[3][2] += a.w*b.z; acc[3][3] += a.w*b.w;
        }
        __syncthreads();
        if (more){ storeT(); __syncthreads(); }
    }

    #pragma unroll
    for (int i=0;i<4;i++){
        int mm = m0 + ty*4 + i;
        if (mm>=M) continue;
        #pragma unroll
        for (int j=0;j<4;j++){
            int nn = n0 + tx*4 + j;
            if (nn>=N) continue;
            float v = acc[i][j];
            if (bias) v += bias[nn];
            if (ep==1) v = gelu_f(v);
            else if (ep==2) v = tanhf(v)*scale;
            C[(long long)mm*ldc + nn] = v;
        }
    }
}

// ---------------- batched matrix transpose: in [R,Cc] -> out [Cc,R] --------
__global__ __launch_bounds__(256) void transpose_kernel(
    const float* __restrict__ in, float* __restrict__ out, int R, int Cc)
{
    __shared__ float tile[32][33];
    const float* inb = in + (size_t)blockIdx.z * R * Cc;
    float* outb = out + (size_t)blockIdx.z * R * Cc;
    int bx = blockIdx.x*32, by = blockIdx.y*32;
    int tx = threadIdx.x, ty = threadIdx.y;
    #pragma unroll
    for (int i=0;i<32;i+=8){
        int r = by+ty+i, c = bx+tx;
        if (r<R && c<Cc) tile[ty+i][tx] = inb[(size_t)r*Cc + c];
    }
    __syncthreads();
    #pragma unroll
    for (int i=0;i<32;i+=8){
        int c = bx+ty+i, r = by+tx;
        if (c<Cc && r<R) outb[(size_t)c*R + r] = tile[tx][ty+i];
    }
}

// ---------------- depthwise 3x3 s2 conv + LayerNorm + GELU (single pass) ---
__global__ __launch_bounds__(384) void dwln_kernel(
    const float* __restrict__ Wdw, const float* __restrict__ bdw,
    const float* __restrict__ ln_g, const float* __restrict__ ln_b)
{
    __shared__ float red1[13], red2[13];
    int p = blockIdx.x;        // b*49 + s
    int b = p/49, s = p - b*49;
    int oy = s/7, ox = s - oy*7;
    int c = threadIdx.x;       // 0..383
    float acc = bdw[c];
    #pragma unroll
    for (int kh=0;kh<3;kh++){
        int iy = oy*2-1+kh;
        if (iy<0 || iy>=14) continue;
        #pragma unroll
        for (int kw=0;kw<3;kw++){
            int ix = ox*2-1+kw;
            if (ix<0 || ix>=14) continue;
            acc += g_t1[((b*196)+iy*14+ix)*384 + c]*Wdw[c*9+kh*3+kw];
        }
    }
    int lane = c & 31, w = c >> 5;
    float s1 = acc, s2 = acc*acc;
    #pragma unroll
    for (int o=16;o;o>>=1){
        s1 += __shfl_xor_sync(0xffffffffu, s1, o);
        s2 += __shfl_xor_sync(0xffffffffu, s2, o);
    }
    if (lane==0){ red1[w] = s1; red2[w] = s2; }
    __syncthreads();
    if (w==0){
        float u1 = (lane<12)? red1[lane] : 0.f;
        float u2 = (lane<12)? red2[lane] : 0.f;
        #pragma unroll
        for (int o=16;o;o>>=1){
            u1 += __shfl_xor_sync(0xffffffffu, u1, o);
            u2 += __shfl_xor_sync(0xffffffffu, u2, o);
        }
        if (lane==0){ red1[12] = u1; red2[12] = u2; }
    }
    __syncthreads();
    float mu  = red1[12]*(1.0f/384.0f);
    float var = red2[12]*(1.0f/384.0f) - mu*mu;
    float d = acc - mu;
    float tn = d * rsqrtf(var + 1e-5f) * ln_g[c] + ln_b[c];
    g_t2[p*384 + c] = gelu_f(tn);
}

// ---------------- attention v3: P staged in smem + co fused ---------------
__global__ __launch_bounds__(256) void attn_kernel(
    const float* __restrict__ bk, const float* __restrict__ posembed,
    const float* __restrict__ Wco)
{
    __shared__ float attnS[12*64];
    __shared__ float Aacc [12*196];
    __shared__ float PnS  [12*196];
    __shared__ float sw   [ST_*4];
    __shared__ float bpy  [ST_], bpx[ST_];
    __shared__ float qbks [12];
    __shared__ float cs   [18];
    __shared__ int   sa   [ST_*4];

    int m = blockIdx.x;
    int b = m / 196, n = m - b*196;
    int ny = n / 14, nx = n - ny*14;
    int tid = threadIdx.x;
    int lane = tid & 31, wid = tid >> 5;

    for (int i = tid; i < 12*196; i += 256) Aacc[i] = 0.f;

    // stage all 12 P rows for token n: coalesced float4 (196 = 49 float4)
    for (int i = tid; i < 12*49; i += 256){
        int h = i / 49, q4 = (i % 49)*4;
        const float* Pn = g_P + (((size_t)(b*12+h)*196 + n)*196);
        float4 v = *(const float4*)&Pn[q4];
        *(float4*)&PnS[h*196 + q4] = v;
    }

    // co[m, o] = tanh(q . Wco[o]) / 14   (warp per output, 18 outputs)
    for (int o = wid; o < 18; o += 8){
        float acc = 0.f;
        #pragma unroll
        for (int k=0;k<12;k++)
            acc += g_q[(size_t)m*384 + lane + 32*k] * Wco[(size_t)o*384 + lane + 32*k];
        #pragma unroll
        for (int of=16;of;of>>=1) acc += __shfl_xor_sync(0xffffffffu, acc, of);
        if (lane==0) cs[o] = tanhf(acc)*(1.0f/14.0f);
    }
    // q . bk per head
    if (tid >= 192 && tid < 204){
        int h = tid - 192;
        float acc = 0.f;
        #pragma unroll 8
        for (int d=0; d<32; d++)
            acc += g_q[m*384 + h*32 + d]*bk[h*32 + d];
        qbks[h] = acc;
    }
    __syncthreads();

    // per-slot sampling setup (needs cs for center slots)
    if (tid < ST_){
        int s = tid;
        float py, px, by, bx;
        if (s < S_){
            int ry = s/7, rx = s - ry*7;
            float offY = g_offp[(b*49+s)*392 + n];
            float offX = g_offp[(b*49+s)*392 + 196 + n];
            float gy = (2.0f*ry)*(2.0f/13.0f) - 1.0f;
            float gx = (2.0f*rx)*(2.0f/13.0f) - 1.0f;
            py = (offY + gy + 1.0f)*6.5f;
            px = (offX + gx + 1.0f)*6.5f;
            by = ((2.0f*ry - (float)ny)*(1.0f/13.0f) - offY + 1.0f)*13.0f;
            bx = ((2.0f*rx - (float)nx)*(1.0f/13.0f) - offX + 1.0f)*13.0f;
        } else {
            int kk = s - S_;
            float coY = cs[kk*2];
            float coX = cs[kk*2 + 1];
            float cpy = fminf(fmaxf((float)ny + c_offy[kk], 0.f), 14.f);
            float cpx = fminf(fmaxf((float)nx + c_offx[kk], 0.f), 14.f);
            float cgy = cpy*(2.0f/13.0f) - 1.0f;
            float cgx = cpx*(2.0f/13.0f) - 1.0f;
            py = (coY + cgy + 1.0f)*6.5f;
            px = (coX + cgx + 1.0f)*6.5f;
            by = (coY - (float)ny + 1.0f)*13.0f;
            bx = (coX - (float)nx + 1.0f)*13.0f;
        }
        bpy[s] = by; bpx[s] = bx;
        float y0f = floorf(py), x0f = floorf(px);
        float wy1 = py - y0f, wx1 = px - x0f;
        int y0 = (int)y0f, x0 = (int)x0f;
        float wts[4] = {(1.f-wy1)*(1.f-wx1), (1.f-wy1)*wx1, wy1*(1.f-wx1), wy1*wx1};
        const int dys[4] = {0,0,1,1};
        const int dxs[4] = {0,1,0,1};
        #pragma unroll
        for (int i=0;i<4;i++){
            int yy = y0+dys[i], xx = x0+dxs[i];
            bool valid = (yy>=0 && yy<=13 && xx>=0 && xx<=13);
            int yc = min(max(yy,0),13), xc = min(max(xx,0),13);
            sw[s*4+i] = valid ? wts[i] : 0.f;
            sa[s*4+i] = yc*14 + xc;
        }
    }
    __syncthreads();

    // logits = rel-pos bias (bilinear) + sum_i w_i * PnS[h][t_i] + q.bk
    for (int p2 = tid; p2 < 12*ST_; p2 += 256){
        int h = p2 / ST_, s = p2 - h*ST_;
        float py = bpy[s], px = bpx[s];
        float y0f = floorf(py), x0f = floorf(px);
        float wy1 = py - y0f, wx1 = px - x0f;
        int y0 = (int)y0f, x0 = (int)x0f;
        const float* tb = posembed + h*729;
        float acc = qbks[h];
        float wts[4] = {(1.f-wy1)*(1.f-wx1), (1.f-wy1)*wx1, wy1*(1.f-wx1), wy1*wx1};
        const int dys[4]={0,0,1,1}, dxs[4]={0,1,0,1};
        #pragma unroll
        for (int i=0;i<4;i++){
            int yy=y0+dys[i], xx=x0+dxs[i];
            if (yy>=0 && yy<=26 && xx>=0 && xx<=26)
                acc += tb[yy*27+xx]*wts[i];
        }
        const float* Pn = PnS + h*196;
        acc += sw[s*4+0]*Pn[sa[s*4+0]] + sw[s*4+1]*Pn[sa[s*4+1]]
             + sw[s*4+2]*Pn[sa[s*4+2]] + sw[s*4+3]*Pn[sa[s*4+3]];
        attnS[h*64+s] = acc;
    }
    __syncthreads();

    for (int h = wid; h < 12; h += 8){
        float v0 = attnS[h*64 + lane];
        float v1 = (lane < ST_-32) ? attnS[h*64 + 32 + lane] : -1e30f;
        float mx = fmaxf(v0, v1);
        #pragma unroll
        for (int o=16;o;o>>=1) mx = fmaxf(mx, __shfl_xor_sync(0xffffffffu, mx, o));
        float e0 = expf(v0 - mx);
        float e1 = (lane < ST_-32) ? expf(v1 - mx) : 0.f;
        float ssum = e0 + e1;
        #pragma unroll
        for (int o=16;o;o>>=1) ssum += __shfl_xor_sync(0xffffffffu, ssum, o);
        float inv = 1.0f/ssum;
        attnS[h*64 + lane] = e0*inv;
        if (lane < ST_-32) attnS[h*64+32+lane] = e1*inv;
    }
    __syncthreads();

    for (int p2 = tid; p2 < 12*ST_; p2 += 256){
        int h = p2 / ST_, s = p2 - h*ST_;
        float a = attnS[h*64+s];
        #pragma unroll
        for (int i=0;i<4;i++)
            atomicAdd(&Aacc[h*196 + sa[s*4+i]], a*sw[s*4+i]);
    }
    __syncthreads();

    for (int i = tid; i < 12*196; i += 256){
        int h = i/196, t = i - h*196;
        g_A[(((size_t)(b*12+h)*196) + n)*196 + t] = Aacc[i];
    }
}

// ---------------------------------------------------------------------------
extern "C" void kernel_launch(void* const* d_in, const int* in_sizes, int n_in,
                              void* d_out, int out_size)
{
    (void)in_sizes; (void)n_in; (void)out_size;
    const float* x   = (const float*)d_in[0];
    const float* Wq  = (const float*)d_in[1];
    const float* bq  = (const float*)d_in[2];
    const float* Wk  = (const float*)d_in[3];
    const float* bk  = (const float*)d_in[4];
    const float* Wv  = (const float*)d_in[5];
    const float* bv  = (const float*)d_in[6];
    const float* Wo1 = (const float*)d_in[7];
    const float* bo1 = (const float*)d_in[8];
    const float* Wdw = (const float*)d_in[9];
    const float* bdw = (const float*)d_in[10];
    const float* ln_g= (const float*)d_in[11];
    const float* ln_b= (const float*)d_in[12];
    const float* Wo2 = (const float*)d_in[13];
    const float* Wco = (const float*)d_in[14];
    const float* pe  = (const float*)d_in[15];
    const float* Wp  = (const float*)d_in[16];
    const float* bp  = (const float*)d_in[17];
    float* out = (float*)d_out;

    float *xh,*q,*t1,*t2,*offp,*Vh,*A,*ov,*y;
    cudaGetSymbolAddress((void**)&xh,  g_xh);
    cudaGetSymbolAddress((void**)&q,   g_q);
    cudaGetSymbolAddress((void**)&t1,  g_t1);
    cudaGetSymbolAddress((void**)&t2,  g_t2);
    cudaGetSymbolAddress((void**)&offp,g_offp);
    cudaGetSymbolAddress((void**)&Vh,  g_Vh);
    cudaGetSymbolAddress((void**)&A,   g_A);
    cudaGetSymbolAddress((void**)&ov,  g_ov);
    cudaGetSymbolAddress((void**)&y,   g_y);

    // static aux stream + events (created once, outside capture)
    static cudaStream_t s_aux = nullptr;
    static cudaEvent_t  eQ = nullptr, eP = nullptr;
    if (!s_aux){
        cudaStreamCreateWithFlags(&s_aux, cudaStreamNonBlocking);
        cudaEventCreateWithFlags(&eQ, cudaEventDisableTiming);
        cudaEventCreateWithFlags(&eP, cudaEventDisableTiming);
    }

    dim3 tb(32,8);

    // 1) x (B,C,H,W) -> xh (B,N,C)
    transpose_kernel<<<dim3(CDIV(196,32), CDIV(384,32), B_), tb>>>(x, xh, 384, 196);

    // 2) q, K0, Vh in one fused launch
    qkv_kernel<<<dim3(6,25,3),256>>>(Wq, bq, Wk, Wv);

    // fork: pk runs on aux stream concurrently with t1->dwln->offp chain
    cudaEventRecord(eQ, 0);
    cudaStreamWaitEvent(s_aux, eQ, 0);

    // 3) t1 = gelu(q @ Wo1^T + bo1)              (main stream)
    gemm_t<64,64><<<dim3(6,25,1),256>>>(q, Wo1, bo1, t1, M_,384,384, 384,384,384,
                                        0,0,0,0, 0,0,0,0, 1, 1, 0.f);
    // 4) P[b,h,n,t] v5                           (aux stream, concurrent)
    pk_kernel<<<dim3(4,96),384,0,s_aux>>>();

    // 5) depthwise conv + LN + gelu -> t2        (main stream)
    dwln_kernel<<<B_*S_, 384>>>(Wdw, bdw, ln_g, ln_b);

    // 6) offp = tanh(t2 @ Wo2^T) * FACTOR/14     (main stream)
    gemm_t<32,32><<<dim3(13,13,1),64>>>(t2, Wo2, nullptr, offp, B_*S_, 392, 384,
                                        384,384,392, 0,0,0,0, 0,0,0,0, 1, 2, 2.0f/14.0f);

    // join: attn needs P
    cudaEventRecord(eP, s_aux);
    cudaStreamWaitEvent(0, eP, 0);

    // 7) attention v3 (P staged in smem) -> A
    attn_kernel<<<M_, 256>>>(bk, pe, Wco);

    // 8) ov[b,n,h*32+d] = sum_t A[b,h,n,t] * Vh[b,h,t,d] + bv
    gemm_t<64,32><<<dim3(1,4,96),128>>>(A, Vh, bv, ov, 196, 32, 196,
                                        196, 32, 384,
                                        12LL*196*196, 12LL*196*32, 196LL*384, 0,
                                        196LL*196, 196LL*32, 32LL, 32LL,
                                        0, 0, 0.f);
    // 9) y = ov @ Wp^T + bp
    gemm_t<64,64><<<dim3(6,25,1),256>>>(ov, Wp, bp, y, M_,384,384, 384,384,384,
                                        0,0,0,0, 0,0,0,0, 1, 0, 0.f);
    // 10) y (B,N,C) -> out (B,C,H,W)
    transpose_kernel<<<dim3(CDIV(384,32), CDIV(196,32), B_), tb>>>(y, out, 196, 384);
}

// round 16
// speedup vs baseline: 1.2278x; 1.0279x over previous
#include <cuda_runtime.h>
#include <math.h>

#define B_ 8
#define C_ 384
#define H_ 14
#define W_ 14
#define N_ 196
#define HEADS_ 12
#define RH_ 7
#define RW_ 7
#define S_ 49
#define ST_ 58
#define M_ (B_*N_)     // 1568

#define CDIV(a,b) (((a)+(b)-1)/(b))

// ---------------- scratch (device globals; no allocation allowed) ----------
__device__ float g_xh[M_*C_];
__device__ float g_q [M_*C_];
__device__ float g_t1[M_*C_];
__device__ float g_t2[B_*S_*C_];
__device__ float g_offp[B_*S_*2*N_];
__device__ float g_co[M_*18];
__device__ float g_K [M_*C_];                       // xh @ Wk^T (no bias)
__device__ float g_Vh[(size_t)B_*HEADS_*N_*32];     // xh @ Wv^T, head-blocked [b,h,t,d]
__device__ float g_P [(size_t)B_*HEADS_*N_*N_];     // q.K0 per (b,h): [n,n']
__device__ float g_A [(size_t)B_*HEADS_*N_*N_];     // attn scattered: [b,h,n,t]
__device__ float g_ov[M_*C_];
__device__ float g_y [M_*C_];

__constant__ float c_offy[9] = {0.f,-1.f,-1.f,-1.f,0.f,1.f,1.f,1.f,0.f};
__constant__ float c_offx[9] = {-1.f,-1.f,0.f,1.f,1.f,1.f,0.f,-1.f,0.f};

__device__ __forceinline__ float gelu_f(float v){
    return 0.5f*v*(1.0f+erff(v*0.70710678118654752f));
}

// ---------------- q/K0/Vh GEMM over shared A = xh (base selects weight) ----
__global__ __launch_bounds__(256) void qkv_kernel(
    const float* __restrict__ Wq, const float* __restrict__ bq,
    const float* __restrict__ Wk, const float* __restrict__ Wv, int base)
{
    __shared__ float As[16][68];
    __shared__ float Bs[16][68];
    const int which = base + blockIdx.z;
    const float* __restrict__ Bm = (which==0) ? Wq : (which==1) ? Wk : Wv;

    const int m0 = blockIdx.y*64, n0 = blockIdx.x*64;
    const int tid = threadIdx.x;
    const int tx = tid & 15, ty = tid >> 4;

    float acc[4][4];
    #pragma unroll
    for (int i=0;i<4;i++)
        #pragma unroll
        for (int j=0;j<4;j++) acc[i][j]=0.f;

    float4 pa, pb;
    const float4 z4 = make_float4(0.f,0.f,0.f,0.f);
    const int r = tid>>2, kc = (tid&3)*4;

    auto loadT = [&](int k0){
        int mm = m0 + r;
        pa = (mm<M_) ? *(const float4*)&g_xh[(size_t)mm*384 + k0 + kc] : z4;
        pb = *(const float4*)&Bm[(size_t)(n0+r)*384 + k0 + kc];
    };
    auto storeT = [&](){
        As[kc+0][r]=pa.x; As[kc+1][r]=pa.y; As[kc+2][r]=pa.z; As[kc+3][r]=pa.w;
        Bs[kc+0][r]=pb.x; Bs[kc+1][r]=pb.y; Bs[kc+2][r]=pb.z; Bs[kc+3][r]=pb.w;
    };

    loadT(0); storeT(); __syncthreads();
    for (int k0=16; k0<=384; k0+=16){
        bool more = (k0 < 384);
        if (more) loadT(k0);
        #pragma unroll
        for (int k=0;k<16;k++){
            float4 a = *(const float4*)&As[k][ty*4];
            float4 b = *(const float4*)&Bs[k][tx*4];
            acc[0][0] += a.x*b.x; acc[0][1] += a.x*b.y; acc[0][2] += a.x*b.z; acc[0][3] += a.x*b.w;
            acc[1][0] += a.y*b.x; acc[1][1] += a.y*b.y; acc[1][2] += a.y*b.z; acc[1][3] += a.y*b.w;
            acc[2][0] += a.z*b.x; acc[2][1] += a.z*b.y; acc[2][2] += a.z*b.z; acc[2][3] += a.z*b.w;
            acc[3][0] += a.w*b.x; acc[3][1] += a.w*b.y; acc[3][2] += a.w*b.z; acc[3][3] += a.w*b.w;
        }
        __syncthreads();
        if (more){ storeT(); __syncthreads(); }
    }

    #pragma unroll
    for (int i=0;i<4;i++){
        int mm = m0 + ty*4 + i;
        if (mm>=M_) continue;
        #pragma unroll
        for (int j=0;j<4;j++){
            int nn = n0 + tx*4 + j;
            float v = acc[i][j];
            if (which==0){
                g_q[(size_t)mm*384 + nn] = v + bq[nn];
            } else if (which==1){
                g_K[(size_t)mm*384 + nn] = v;
            } else {
                int bb = mm/196, t = mm - bb*196;
                int hh = nn>>5,  d = nn & 31;
                g_Vh[(((size_t)(bb*12+hh)*196) + t)*32 + d] = v;
            }
        }
    }
}

// ---------------- specialized P kernel v5: float4 fill + 1 tile/thread -----
__global__ __launch_bounds__(384) void pk_kernel()
{
    __shared__ float qT[32][52];
    __shared__ float kT[32][200];
    const int bh = blockIdx.y;
    const int b  = bh / 12, h = bh - b*12;
    const int n0 = blockIdx.x * 49;
    const int tid = threadIdx.x;
    const float4 z4 = make_float4(0.f,0.f,0.f,0.f);

    for (int i = tid; i < 52*8; i += 384){
        int n = i >> 3, k4 = (i & 7)*4;
        float4 v = (n < 49) ? *(const float4*)&g_q[((size_t)(b*196 + n0 + n))*384 + h*32 + k4] : z4;
        qT[k4+0][n]=v.x; qT[k4+1][n]=v.y; qT[k4+2][n]=v.z; qT[k4+3][n]=v.w;
    }
    for (int i = tid; i < 200*8; i += 384){
        int t = i >> 3, k4 = (i & 7)*4;
        float4 v = (t < 196) ? *(const float4*)&g_K[((size_t)(b*196 + t))*384 + h*32 + k4] : z4;
        kT[k4+0][t]=v.x; kT[k4+1][t]=v.y; kT[k4+2][t]=v.z; kT[k4+3][t]=v.w;
    }
    __syncthreads();

    if (tid < 325){
        int tn = tid % 13, tt = tid / 13;
        int nn = tn*4, t8 = tt*8;
        float a0[8] = {0,0,0,0,0,0,0,0};
        float a1[8] = {0,0,0,0,0,0,0,0};
        float a2[8] = {0,0,0,0,0,0,0,0};
        float a3[8] = {0,0,0,0,0,0,0,0};
        #pragma unroll 4
        for (int k=0;k<32;k++){
            float4 a  = *(const float4*)&qT[k][nn];
            float4 v0 = *(const float4*)&kT[k][t8];
            float4 v1 = *(const float4*)&kT[k][t8+4];
            a0[0]+=a.x*v0.x; a0[1]+=a.x*v0.y; a0[2]+=a.x*v0.z; a0[3]+=a.x*v0.w;
            a0[4]+=a.x*v1.x; a0[5]+=a.x*v1.y; a0[6]+=a.x*v1.z; a0[7]+=a.x*v1.w;
            a1[0]+=a.y*v0.x; a1[1]+=a.y*v0.y; a1[2]+=a.y*v0.z; a1[3]+=a.y*v0.w;
            a1[4]+=a.y*v1.x; a1[5]+=a.y*v1.y; a1[6]+=a.y*v1.z; a1[7]+=a.y*v1.w;
            a2[0]+=a.z*v0.x; a2[1]+=a.z*v0.y; a2[2]+=a.z*v0.z; a2[3]+=a.z*v0.w;
            a2[4]+=a.z*v1.x; a2[5]+=a.z*v1.y; a2[6]+=a.z*v1.z; a2[7]+=a.z*v1.w;
            a3[0]+=a.w*v0.x; a3[1]+=a.w*v0.y; a3[2]+=a.w*v0.z; a3[3]+=a.w*v0.w;
            a3[4]+=a.w*v1.x; a3[5]+=a.w*v1.y; a3[6]+=a.w*v1.z; a3[7]+=a.w*v1.w;
        }
        bool full = (t8 < 192);
        size_t base = ((size_t)bh*196 + n0 + nn)*196 + t8;
        float* rows[4] = {a0,a1,a2,a3};
        #pragma unroll
        for (int r=0;r<4;r++){
            if (nn+r >= 49) break;
            float* ar = rows[r];
            *(float4*)&g_P[base + (size_t)r*196] =
                make_float4(ar[0],ar[1],ar[2],ar[3]);
            if (full)
                *(float4*)&g_P[base + (size_t)r*196 + 4] =
                    make_float4(ar[4],ar[5],ar[6],ar[7]);
        }
    }
}

// ---------------- templated batched tiled GEMM (general) -------------------
template<int BM, int BN>
__global__ __launch_bounds__((BM/4)*(BN/4)) void gemm_t(
    const float* __restrict__ A, const float* __restrict__ Bm,
    const float* __restrict__ bias, float* __restrict__ C,
    int M, int N, int K, int lda, int ldb, int ldc,
    long long aB, long long bB, long long cB, long long biasB,
    long long aH, long long bH, long long cH, long long biasH,
    int transB, int ep, float scale)
{
    constexpr int T  = (BM/4)*(BN/4);
    constexpr int NA = (BM*4)/T;
    constexpr int NB = (BN*4)/T;
    __shared__ float As[16][BM+4];
    __shared__ float Bs[16][BN+4];

    const int zb = blockIdx.z / 12, zh = blockIdx.z % 12;
    A  += zb*aB + zh*aH;
    Bm += zb*bB + zh*bH;
    C  += zb*cB + zh*cH;
    if (bias) bias += zb*biasB + zh*biasH;

    const int m0 = blockIdx.y*BM, n0 = blockIdx.x*BN;
    const int tid = threadIdx.x;
    const int tx = tid % (BN/4), ty = tid / (BN/4);

    float acc[4][4];
    #pragma unroll
    for (int i=0;i<4;i++)
        #pragma unroll
        for (int j=0;j<4;j++) acc[i][j]=0.f;

    float4 pa[NA], pb[NB];
    const float4 z4 = make_float4(0.f,0.f,0.f,0.f);

    auto loadT = [&](int k0){
        #pragma unroll
        for (int u=0;u<NA;u++){
            int f = tid + u*T;
            int r = f>>2, kc = (f&3)*4;
            int mm = m0 + r;
            pa[u] = (mm<M && k0+kc<K) ? *(const float4*)&A[(long long)mm*lda + k0 + kc] : z4;
        }
        if (transB){
            #pragma unroll
            for (int u=0;u<NB;u++){
                int f = tid + u*T;
                int r = f>>2, kc = (f&3)*4;
                int nn = n0 + r;
                pb[u] = (nn<N && k0+kc<K) ? *(const float4*)&Bm[(long long)nn*ldb + k0 + kc] : z4;
            }
        } else {
            #pragma unroll
            for (int u=0;u<NB;u++){
                int f = tid + u*T;
                int kk = f/(BN/4), nc = (f%(BN/4))*4;
                int nn = n0 + nc;
                pb[u] = (k0+kk<K && nn<N) ? *(const float4*)&Bm[(long long)(k0+kk)*ldb + nn] : z4;
            }
        }
    };
    auto storeT = [&](){
        #pragma unroll
        for (int u=0;u<NA;u++){
            int f = tid + u*T;
            int r = f>>2, kc = (f&3)*4;
            As[kc+0][r]=pa[u].x; As[kc+1][r]=pa[u].y;
            As[kc+2][r]=pa[u].z; As[kc+3][r]=pa[u].w;
        }
        if (transB){
            #pragma unroll
            for (int u=0;u<NB;u++){
                int f = tid + u*T;
                int r = f>>2, kc = (f&3)*4;
                Bs[kc+0][r]=pb[u].x; Bs[kc+1][r]=pb[u].y;
                Bs[kc+2][r]=pb[u].z; Bs[kc+3][r]=pb[u].w;
            }
        } else {
            #pragma unroll
            for (int u=0;u<NB;u++){
                int f = tid + u*T;
                int kk = f/(BN/4), nc = (f%(BN/4))*4;
                *(float4*)&Bs[kk][nc] = pb[u];
            }
        }
    };

    const int KT = CDIV(K,16)*16;
    loadT(0); storeT(); __syncthreads();
    for (int k0=16; k0<=KT; k0+=16){
        bool more = (k0 < KT);
        if (more) loadT(k0);
        #pragma unroll
        for (int k=0;k<16;k++){
            float4 a = *(const float4*)&As[k][ty*4];
            float4 b = *(const float4*)&Bs[k][tx*4];
            acc[0][0] += a.x*b.x; acc[0][1] += a.x*b.y; acc[0][2] += a.x*b.z; acc[0][3] += a.x*b.w;
            acc[1][0] += a.y*b.x; acc[1][1] += a.y*b.y; acc[1][2] += a.y*b.z; acc[1][3] += a.y*b.w;
            acc[2][0] += a.z*b.x; acc[2][1] += a.z*b.y; acc[2][2] += a.z*b.z; acc[2][3] += a.z*b.w;
            acc[3][0] += a.w*b.x; acc[3][1] += a.w*b.y; acc[3][2] += a.w*b.z; acc[3][3] += a.w*b.w;
        }
        __syncthreads();
        if (more){ storeT(); __syncthreads(); }
    }

    #pragma unroll
    for (int i=0;i<4;i++){
        int mm = m0 + ty*4 + i;
        if (mm>=M) continue;
        #pragma unroll
        for (int j=0;j<4;j++){
            int nn = n0 + tx*4 + j;
            if (nn>=N) continue;
            float v = acc[i][j];
            if (bias) v += bias[nn];
            if (ep==1) v = gelu_f(v);
            else if (ep==2) v = tanhf(v)*scale;
            C[(long long)mm*ldc + nn] = v;
        }
    }
}

// ---------------- batched matrix transpose: in [R,Cc] -> out [Cc,R] --------
__global__ __launch_bounds__(256) void transpose_kernel(
    const float* __restrict__ in, float* __restrict__ out, int R, int Cc)
{
    __shared__ float tile[32][33];
    const float* inb = in + (size_t)blockIdx.z * R * Cc;
    float* outb = out + (size_t)blockIdx.z * R * Cc;
    int bx = blockIdx.x*32, by = blockIdx.y*32;
    int tx = threadIdx.x, ty = threadIdx.y;
    #pragma unroll
    for (int i=0;i<32;i+=8){
        int r = by+ty+i, c = bx+tx;
        if (r<R && c<Cc) tile[ty+i][tx] = inb[(size_t)r*Cc + c];
    }
    __syncthreads();
    #pragma unroll
    for (int i=0;i<32;i+=8){
        int c = bx+ty+i, r = by+tx;
        if (c<Cc && r<R) outb[(size_t)c*R + r] = tile[tx][ty+i];
    }
}

// ---------------- depthwise 3x3 s2 conv + LayerNorm + GELU (single pass) ---
__global__ __launch_bounds__(384) void dwln_kernel(
    const float* __restrict__ Wdw, const float* __restrict__ bdw,
    const float* __restrict__ ln_g, const float* __restrict__ ln_b)
{
    __shared__ float red1[13], red2[13];
    int p = blockIdx.x;        // b*49 + s
    int b = p/49, s = p - b*49;
    int oy = s/7, ox = s - oy*7;
    int c = threadIdx.x;       // 0..383
    float acc = bdw[c];
    #pragma unroll
    for (int kh=0;kh<3;kh++){
        int iy = oy*2-1+kh;
        if (iy<0 || iy>=14) continue;
        #pragma unroll
        for (int kw=0;kw<3;kw++){
            int ix = ox*2-1+kw;
            if (ix<0 || ix>=14) continue;
            acc += g_t1[((b*196)+iy*14+ix)*384 + c]*Wdw[c*9+kh*3+kw];
        }
    }
    int lane = c & 31, w = c >> 5;
    float s1 = acc, s2 = acc*acc;
    #pragma unroll
    for (int o=16;o;o>>=1){
        s1 += __shfl_xor_sync(0xffffffffu, s1, o);
        s2 += __shfl_xor_sync(0xffffffffu, s2, o);
    }
    if (lane==0){ red1[w] = s1; red2[w] = s2; }
    __syncthreads();
    if (w==0){
        float u1 = (lane<12)? red1[lane] : 0.f;
        float u2 = (lane<12)? red2[lane] : 0.f;
        #pragma unroll
        for (int o=16;o;o>>=1){
            u1 += __shfl_xor_sync(0xffffffffu, u1, o);
            u2 += __shfl_xor_sync(0xffffffffu, u2, o);
        }
        if (lane==0){ red1[12] = u1; red2[12] = u2; }
    }
    __syncthreads();
    float mu  = red1[12]*(1.0f/384.0f);
    float var = red2[12]*(1.0f/384.0f) - mu*mu;
    float d = acc - mu;
    float tn = d * rsqrtf(var + 1e-5f) * ln_g[c] + ln_b[c];
    g_t2[p*384 + c] = gelu_f(tn);
}

// ---------------- attention v4: P staged in smem, co precomputed ----------
__global__ __launch_bounds__(256) void attn_kernel(
    const float* __restrict__ bk, const float* __restrict__ posembed)
{
    __shared__ float attnS[12*64];
    __shared__ float Aacc [12*196];
    __shared__ float PnS  [12*196];
    __shared__ float sw   [ST_*4];
    __shared__ float bpy  [ST_], bpx[ST_];
    __shared__ float qbks [12];
    __shared__ int   sa   [ST_*4];

    int m = blockIdx.x;
    int b = m / 196, n = m - b*196;
    int ny = n / 14, nx = n - ny*14;
    int tid = threadIdx.x;
    int lane = tid & 31, wid = tid >> 5;

    for (int i = tid; i < 12*196; i += 256) Aacc[i] = 0.f;

    // stage all 12 P rows for token n: coalesced float4 (196 = 49 float4)
    for (int i = tid; i < 12*49; i += 256){
        int h = i / 49, q4 = (i % 49)*4;
        const float* Pn = g_P + (((size_t)(b*12+h)*196 + n)*196);
        float4 v = *(const float4*)&Pn[q4];
        *(float4*)&PnS[h*196 + q4] = v;
    }

    // q . bk per head
    if (tid >= 192 && tid < 204){
        int h = tid - 192;
        float acc = 0.f;
        #pragma unroll 8
        for (int d=0; d<32; d++)
            acc += g_q[m*384 + h*32 + d]*bk[h*32 + d];
        qbks[h] = acc;
    }

    // per-slot sampling setup (co precomputed in g_co)
    if (tid < ST_){
        int s = tid;
        float py, px, by, bx;
        if (s < S_){
            int ry = s/7, rx = s - ry*7;
            float offY = g_offp[(b*49+s)*392 + n];
            float offX = g_offp[(b*49+s)*392 + 196 + n];
            float gy = (2.0f*ry)*(2.0f/13.0f) - 1.0f;
            float gx = (2.0f*rx)*(2.0f/13.0f) - 1.0f;
            py = (offY + gy + 1.0f)*6.5f;
            px = (offX + gx + 1.0f)*6.5f;
            by = ((2.0f*ry - (float)ny)*(1.0f/13.0f) - offY + 1.0f)*13.0f;
            bx = ((2.0f*rx - (float)nx)*(1.0f/13.0f) - offX + 1.0f)*13.0f;
        } else {
            int kk = s - S_;
            float coY = g_co[m*18 + kk*2];
            float coX = g_co[m*18 + kk*2 + 1];
            float cpy = fminf(fmaxf((float)ny + c_offy[kk], 0.f), 14.f);
            float cpx = fminf(fmaxf((float)nx + c_offx[kk], 0.f), 14.f);
            float cgy = cpy*(2.0f/13.0f) - 1.0f;
            float cgx = cpx*(2.0f/13.0f) - 1.0f;
            py = (coY + cgy + 1.0f)*6.5f;
            px = (coX + cgx + 1.0f)*6.5f;
            by = (coY - (float)ny + 1.0f)*13.0f;
            bx = (coX - (float)nx + 1.0f)*13.0f;
        }
        bpy[s] = by; bpx[s] = bx;
        float y0f = floorf(py), x0f = floorf(px);
        float wy1 = py - y0f, wx1 = px - x0f;
        int y0 = (int)y0f, x0 = (int)x0f;
        float wts[4] = {(1.f-wy1)*(1.f-wx1), (1.f-wy1)*wx1, wy1*(1.f-wx1), wy1*wx1};
        const int dys[4] = {0,0,1,1};
        const int dxs[4] = {0,1,0,1};
        #pragma unroll
        for (int i=0;i<4;i++){
            int yy = y0+dys[i], xx = x0+dxs[i];
            bool valid = (yy>=0 && yy<=13 && xx>=0 && xx<=13);
            int yc = min(max(yy,0),13), xc = min(max(xx,0),13);
            sw[s*4+i] = valid ? wts[i] : 0.f;
            sa[s*4+i] = yc*14 + xc;
        }
    }
    __syncthreads();

    // logits = rel-pos bias (bilinear) + sum_i w_i * PnS[h][t_i] + q.bk
    for (int p2 = tid; p2 < 12*ST_; p2 += 256){
        int h = p2 / ST_, s = p2 - h*ST_;
        float py = bpy[s], px = bpx[s];
        float y0f = floorf(py), x0f = floorf(px);
        float wy1 = py - y0f, wx1 = px - x0f;
        int y0 = (int)y0f, x0 = (int)x0f;
        const float* tb = posembed + h*729;
        float acc = qbks[h];
        float wts[4] = {(1.f-wy1)*(1.f-wx1), (1.f-wy1)*wx1, wy1*(1.f-wx1), wy1*wx1};
        const int dys[4]={0,0,1,1}, dxs[4]={0,1,0,1};
        #pragma unroll
        for (int i=0;i<4;i++){
            int yy=y0+dys[i], xx=x0+dxs[i];
            if (yy>=0 && yy<=26 && xx>=0 && xx<=26)
                acc += tb[yy*27+xx]*wts[i];
        }
        const float* Pn = PnS + h*196;
        acc += sw[s*4+0]*Pn[sa[s*4+0]] + sw[s*4+1]*Pn[sa[s*4+1]]
             + sw[s*4+2]*Pn[sa[s*4+2]] + sw[s*4+3]*Pn[sa[s*4+3]];
        attnS[h*64+s] = acc;
    }
    __syncthreads();

    for (int h = wid; h < 12; h += 8){
        float v0 = attnS[h*64 + lane];
        float v1 = (lane < ST_-32) ? attnS[h*64 + 32 + lane] : -1e30f;
        float mx = fmaxf(v0, v1);
        #pragma unroll
        for (int o=16;o;o>>=1) mx = fmaxf(mx, __shfl_xor_sync(0xffffffffu, mx, o));
        float e0 = expf(v0 - mx);
        float e1 = (lane < ST_-32) ? expf(v1 - mx) : 0.f;
        float ssum = e0 + e1;
        #pragma unroll
        for (int o=16;o;o>>=1) ssum += __shfl_xor_sync(0xffffffffu, ssum, o);
        float inv = 1.0f/ssum;
        attnS[h*64 + lane] = e0*inv;
        if (lane < ST_-32) attnS[h*64+32+lane] = e1*inv;
    }
    __syncthreads();

    for (int p2 = tid; p2 < 12*ST_; p2 += 256){
        int h = p2 / ST_, s = p2 - h*ST_;
        float a = attnS[h*64+s];
        #pragma unroll
        for (int i=0;i<4;i++)
            atomicAdd(&Aacc[h*196 + sa[s*4+i]], a*sw[s*4+i]);
    }
    __syncthreads();

    for (int i = tid; i < 12*196; i += 256){
        int h = i/196, t = i - h*196;
        g_A[(((size_t)(b*12+h)*196) + n)*196 + t] = Aacc[i];
    }
}

// ---------------------------------------------------------------------------
extern "C" void kernel_launch(void* const* d_in, const int* in_sizes, int n_in,
                              void* d_out, int out_size)
{
    (void)in_sizes; (void)n_in; (void)out_size;
    const float* x   = (const float*)d_in[0];
    const float* Wq  = (const float*)d_in[1];
    const float* bq  = (const float*)d_in[2];
    const float* Wk  = (const float*)d_in[3];
    const float* bk  = (const float*)d_in[4];
    const float* Wv  = (const float*)d_in[5];
    const float* bv  = (const float*)d_in[6];
    const float* Wo1 = (const float*)d_in[7];
    const float* bo1 = (const float*)d_in[8];
    const float* Wdw = (const float*)d_in[9];
    const float* bdw = (const float*)d_in[10];
    const float* ln_g= (const float*)d_in[11];
    const float* ln_b= (const float*)d_in[12];
    const float* Wo2 = (const float*)d_in[13];
    const float* Wco = (const float*)d_in[14];
    const float* pe  = (const float*)d_in[15];
    const float* Wp  = (const float*)d_in[16];
    const float* bp  = (const float*)d_in[17];
    float* out = (float*)d_out;

    float *xh,*q,*t1,*t2,*offp,*co,*Vh,*A,*ov,*y;
    cudaGetSymbolAddress((void**)&xh,  g_xh);
    cudaGetSymbolAddress((void**)&q,   g_q);
    cudaGetSymbolAddress((void**)&t1,  g_t1);
    cudaGetSymbolAddress((void**)&t2,  g_t2);
    cudaGetSymbolAddress((void**)&offp,g_offp);
    cudaGetSymbolAddress((void**)&co,  g_co);
    cudaGetSymbolAddress((void**)&Vh,  g_Vh);
    cudaGetSymbolAddress((void**)&A,   g_A);
    cudaGetSymbolAddress((void**)&ov,  g_ov);
    cudaGetSymbolAddress((void**)&y,   g_y);

    // static aux streams + events (created once, outside capture)
    static cudaStream_t s_aux1 = nullptr, s_aux2 = nullptr;
    static cudaEvent_t  eT = nullptr, eQ = nullptr, eP = nullptr, eCV = nullptr;
    if (!s_aux1){
        cudaStreamCreateWithFlags(&s_aux1, cudaStreamNonBlocking);
        cudaStreamCreateWithFlags(&s_aux2, cudaStreamNonBlocking);
        cudaEventCreateWithFlags(&eT,  cudaEventDisableTiming);
        cudaEventCreateWithFlags(&eQ,  cudaEventDisableTiming);
        cudaEventCreateWithFlags(&eP,  cudaEventDisableTiming);
        cudaEventCreateWithFlags(&eCV, cudaEventDisableTiming);
    }

    dim3 tb(32,8);

    // 1) x (B,C,H,W) -> xh (B,N,C)                      [main]
    transpose_kernel<<<dim3(CDIV(196,32), CDIV(384,32), B_), tb>>>(x, xh, 384, 196);
    cudaEventRecord(eT, 0);

    // 2) q + K0 only                                    [main]
    qkv_kernel<<<dim3(6,25,2),256>>>(Wq, bq, Wk, Wv, 0);
    cudaEventRecord(eQ, 0);
    cudaStreamWaitEvent(s_aux1, eQ, 0);

    // 3) t1 = gelu(q @ Wo1^T + bo1)                     [main]
    gemm_t<64,64><<<dim3(6,25,1),256>>>(q, Wo1, bo1, t1, M_,384,384, 384,384,384,
                                        0,0,0,0, 0,0,0,0, 1, 1, 0.f);
    // 4) P = q.K0                                       [aux1, profiled slot]
    pk_kernel<<<dim3(4,96),384,0,s_aux1>>>();
    cudaEventRecord(eP, s_aux1);

    // 5) Vh = xh @ Wv^T (only needs transpose)          [aux2]
    cudaStreamWaitEvent(s_aux2, eT, 0);
    qkv_kernel<<<dim3(6,25,1),256,0,s_aux2>>>(Wq, bq, Wk, Wv, 2);
    // 6) co = tanh(q @ Wco^T)/14 (needs q)              [aux2]
    cudaStreamWaitEvent(s_aux2, eQ, 0);
    gemm_t<32,32><<<dim3(1,49,1),64,0,s_aux2>>>(q, Wco, nullptr, co, M_, 18, 384,
                                        384,384,18, 0,0,0,0, 0,0,0,0, 1, 2, 1.0f/14.0f);
    cudaEventRecord(eCV, s_aux2);

    // 7) depthwise conv + LN + gelu -> t2               [main]
    dwln_kernel<<<B_*S_, 384>>>(Wdw, bdw, ln_g, ln_b);

    // 8) offp = tanh(t2 @ Wo2^T) * FACTOR/14            [main]
    gemm_t<32,32><<<dim3(13,13,1),64>>>(t2, Wo2, nullptr, offp, B_*S_, 392, 384,
                                        384,384,392, 0,0,0,0, 0,0,0,0, 1, 2, 2.0f/14.0f);

    // join: attn needs P + co; AV needs Vh (covered by eCV)
    cudaStreamWaitEvent(0, eP, 0);
    cudaStreamWaitEvent(0, eCV, 0);

    // 9) attention v4 -> A                              [main]
    attn_kernel<<<M_, 256>>>(bk, pe);

    // 10) ov = A @ Vh + bv                              [main]
    gemm_t<64,32><<<dim3(1,4,96),128>>>(A, Vh, bv, ov, 196, 32, 196,
                                        196, 32, 384,
                                        12LL*196*196, 12LL*196*32, 196LL*384, 0,
                                        196LL*196, 196LL*32, 32LL, 32LL,
                                        0, 0, 0.f);
    // 11) y = ov @ Wp^T + bp                            [main]
    gemm_t<64,64><<<dim3(6,25,1),256>>>(ov, Wp, bp, y, M_,384,384, 384,384,384,
                                        0,0,0,0, 0,0,0,0, 1, 0, 0.f);
    // 12) y (B,N,C) -> out (B,C,H,W)                    [main]
    transpose_kernel<<<dim3(CDIV(384,32), CDIV(196,32), B_), tb>>>(y, out, 196, 384);
}